// round 6
// baseline (speedup 1.0000x reference)
#include <cuda_runtime.h>
#include <cuda_bf16.h>
#include <cuda_fp16.h>
#include <cstdint>
#include <math.h>

#define BB 8
#define LL 2048
#define DD 512
#define BL (BB*LL)

// ---------------------------------------------------------------------------
// Device scratch (static allocations — allowed)
// ---------------------------------------------------------------------------
__device__ __align__(256) __nv_bfloat16 g_Eh[(size_t)BB*LL*LL];  // exp(S) hi (bf16: range!)
__device__ __align__(256) __nv_bfloat16 g_El[(size_t)BB*LL*LL];  // exp(S) lo
__device__ __align__(256) __half g_Ph[(size_t)BB*LL*LL];         // P = E/Z hi (fp16)
__device__ __align__(256) __half g_Pl[(size_t)BB*LL*LL];         // P lo
__device__ __align__(256) __half g_qh[BL*DD], g_ql[BL*DD];
__device__ __align__(256) __half g_kh[BL*DD], g_kl[BL*DD];
__device__ __align__(256) __half g_vh[BL*DD], g_vl[BL*DD];
__device__ __align__(256) __half g_Wqh[DD*DD], g_Wql[DD*DD];
__device__ __align__(256) __half g_Wkh[DD*DD], g_Wkl[DD*DD];
__device__ __align__(256) __half g_Wvh[DD*DD], g_Wvl[DD*DD];
__device__ __align__(256) __half g_qph[BL*DD], g_qpl[BL*DD];
__device__ __align__(256) __half g_kph[BL*DD], g_kpl[BL*DD];
__device__ __align__(256) __half g_vpTh[BL*DD];                  // [B][D][L], single plane
__device__ __align__(256) float g_crcpz[BL];
__device__ __align__(256) float g_pz[16*BL];

// ---------------------------------------------------------------------------
// Portable PTX helpers (sm_80+ only)
// ---------------------------------------------------------------------------
__device__ __forceinline__ uint32_t smem_u32(const void* p) {
    uint32_t a;
    asm("{ .reg .u64 t; cvta.to.shared.u64 t, %1; cvt.u32.u64 %0, t; }"
        : "=r"(a) : "l"(p));
    return a;
}

#define CP16(dst, src) \
    asm volatile("cp.async.cg.shared.global [%0], [%1], 16;" \
                 :: "r"(dst), "l"(src) : "memory")
#define CP_COMMIT() asm volatile("cp.async.commit_group;" ::: "memory")
#define CP_WAIT2()  asm volatile("cp.async.wait_group 2;" ::: "memory")

#define LDSM4(r0, r1, r2, r3, addr) \
    asm volatile("ldmatrix.sync.aligned.m8n8.x4.shared.b16 {%0,%1,%2,%3}, [%4];" \
                 : "=r"(r0), "=r"(r1), "=r"(r2), "=r"(r3) : "r"(addr))

#define MMAH(d, a, b) \
    asm volatile("mma.sync.aligned.m16n8k16.row.col.f32.f16.f16.f32 " \
                 "{%0,%1,%2,%3}, {%4,%5,%6,%7}, {%8,%9}, {%0,%1,%2,%3};" \
                 : "+f"((d)[0]), "+f"((d)[1]), "+f"((d)[2]), "+f"((d)[3]) \
                 : "r"((a)[0]), "r"((a)[1]), "r"((a)[2]), "r"((a)[3]), \
                   "r"((b)[0]), "r"((b)[1]))

__device__ __forceinline__ uint32_t packh2(float a, float b) {
    __half2 t = __floats2half2_rn(a, b);
    uint32_t u; memcpy(&u, &t, 4); return u;
}
// fp16 hi/lo split
__device__ __forceinline__ void split2h(float v0, float v1,
                                        uint32_t& h, uint32_t& l) {
    float h0 = __half2float(__float2half_rn(v0));
    float h1 = __half2float(__float2half_rn(v1));
    h = packh2(v0, v1);
    l = packh2(v0 - h0, v1 - h1);
}
// bf16 hi/lo split (E only)
__device__ __forceinline__ void split2b(float v0, float v1,
                                        uint32_t& h, uint32_t& l) {
    __nv_bfloat16 h0 = __float2bfloat16(v0);
    __nv_bfloat16 h1 = __float2bfloat16(v1);
    __nv_bfloat162 th; th.x = h0; th.y = h1;
    memcpy(&h, &th, 4);
    __nv_bfloat162 tl;
    tl.x = __float2bfloat16(v0 - __bfloat162float(h0));
    tl.y = __float2bfloat16(v1 - __bfloat162float(h1));
    memcpy(&l, &tl, 4);
}

// Fast exp on the FMA pipe (rel err ~2e-6)
__device__ __forceinline__ float fast_exp(float x) {
    float y = x * 1.4426950408889634f;
    float t = y + 12582912.f;
    int   n = __float_as_int(t) - 0x4B400000;
    t -= 12582912.f;
    float f = y - t;
    float p = 1.3333558146e-3f;
    p = fmaf(p, f, 9.6181291076e-3f);
    p = fmaf(p, f, 5.5504108664e-2f);
    p = fmaf(p, f, 2.4022650696e-1f);
    p = fmaf(p, f, 6.9314718056e-1f);
    p = fmaf(p, f, 1.0f);
    return __int_as_float(__float_as_int(p) + (n << 23));
}

// smem: 4 stages x 4 planes x 8KB
#define PL_AH 0
#define PL_AL 8192
#define PL_BH 16384
#define PL_BL 24576
#define STAGE_BYTES 32768
#define SMEM_BYTES 131072

__device__ __forceinline__ uint32_t swz(int r, int kc) {
    return (uint32_t)(r * 64 + ((kc ^ ((r >> 1) & 3)) << 4));
}

// ---------------------------------------------------------------------------
// NT GEMM, fp16 split precision via mma.sync.m16n8k16.
// TERMS=3: Ah*Bh + Ah*Bl + Al*Bh.  TERMS=2: Ah*Bh + Al*Bh (Bl unused).
// mode 0: Cf fp32 row-major.
// mode 1: Ch/Cl fp16 planes row-major (+bias).
// mode 2: Ch fp16 SINGLE plane transposed -> [b][n][m%LL] (+bias).
// mode 3: Ch/Cl = exp(C) bf16 planes row-major + per-tile colsums -> g_pz.
// ---------------------------------------------------------------------------
template<int TERMS>
__global__ void __launch_bounds__(256) gemm_mma(
    const uint16_t* __restrict__ Ah, const uint16_t* __restrict__ Al,
    const uint16_t* __restrict__ Bh, const uint16_t* __restrict__ Bl,
    const float* __restrict__ bias,
    float* __restrict__ Cf,
    uint16_t* __restrict__ Ch, uint16_t* __restrict__ Cl,
    int N, int K,
    size_t sAz, size_t sBz, size_t sCz,
    int mode)
{
    extern __shared__ char smem[];
    const uint32_t sbase = smem_u32(smem);
    const int tid  = threadIdx.x;
    const int lane = tid & 31;
    const int warp = tid >> 5;
    const int wm = (warp >> 1) * 32;
    const int wn = (warp & 1) * 64;
    const int m0 = blockIdx.y * 128, n0 = blockIdx.x * 128, bz = blockIdx.z;

    const uint16_t* pAh = Ah + bz * sAz + (size_t)m0 * K;
    const uint16_t* pAl = Al + bz * sAz + (size_t)m0 * K;
    const uint16_t* pBh = Bh + bz * sBz + (size_t)n0 * K;
    const uint16_t* pBl = (TERMS == 3) ? Bl + bz * sBz + (size_t)n0 * K : nullptr;

    float acc[2][8][4];
    #pragma unroll
    for (int i = 0; i < 2; i++)
        #pragma unroll
        for (int j = 0; j < 8; j++)
            #pragma unroll
            for (int c = 0; c < 4; c++) acc[i][j][c] = 0.f;

#define LOAD_STAGE(buf, kt) do { \
    uint32_t so_ = sbase + (uint32_t)(buf) * STAGE_BYTES; \
    size_t ko_ = (size_t)(kt) * 32; \
    _Pragma("unroll") \
    for (int i_ = 0; i_ < 2; i_++) { \
        int idx_ = tid + i_ * 256; \
        int r_ = idx_ >> 2, c_ = idx_ & 3; \
        uint32_t d_ = so_ + swz(r_, c_); \
        size_t g_ = (size_t)r_ * K + ko_ + c_ * 8; \
        CP16(d_ + PL_AH, pAh + g_); \
        CP16(d_ + PL_AL, pAl + g_); \
        CP16(d_ + PL_BH, pBh + g_); \
        if (TERMS == 3) CP16(d_ + PL_BL, pBl + g_); \
    } \
} while (0)

    const int nk = K >> 5;
    #pragma unroll
    for (int p = 0; p < 3; p++) {
        if (p < nk) LOAD_STAGE(p, p);
        CP_COMMIT();
    }

    for (int kt = 0; kt < nk; kt++) {
        CP_WAIT2();
        __syncthreads();
        if (kt + 3 < nk) LOAD_STAGE((kt + 3) & 3, kt + 3);
        CP_COMMIT();

        const uint32_t so = sbase + (uint32_t)(kt & 3) * STAGE_BYTES;
        #pragma unroll
        for (int ks = 0; ks < 2; ks++) {
            uint32_t a_h[2][4], a_l[2][4];
            const int kc = ks * 2 + (lane >> 4);
            #pragma unroll
            for (int im = 0; im < 2; im++) {
                int rr = wm + im * 16 + (lane & 7) + ((lane >> 3) & 1) * 8;
                uint32_t ad = so + swz(rr, kc);
                LDSM4(a_h[im][0], a_h[im][1], a_h[im][2], a_h[im][3], ad + PL_AH);
                LDSM4(a_l[im][0], a_l[im][1], a_l[im][2], a_l[im][3], ad + PL_AL);
            }
            uint32_t b_h[8][2], b_l[8][2];
            #pragma unroll
            for (int j4 = 0; j4 < 4; j4++) {
                int rr = wn + j4 * 16 + (lane & 7) + ((lane >> 3) & 1) * 8;
                uint32_t bd = so + swz(rr, kc);
                LDSM4(b_h[2*j4][0], b_h[2*j4+1][0], b_h[2*j4][1], b_h[2*j4+1][1],
                      bd + PL_BH);
                if (TERMS == 3)
                    LDSM4(b_l[2*j4][0], b_l[2*j4+1][0], b_l[2*j4][1], b_l[2*j4+1][1],
                          bd + PL_BL);
            }
            #pragma unroll
            for (int im = 0; im < 2; im++)
                #pragma unroll
                for (int j = 0; j < 8; j++) MMAH(acc[im][j], a_h[im], b_h[j]);
            if (TERMS == 3) {
                #pragma unroll
                for (int im = 0; im < 2; im++)
                    #pragma unroll
                    for (int j = 0; j < 8; j++) MMAH(acc[im][j], a_h[im], b_l[j]);
            }
            #pragma unroll
            for (int im = 0; im < 2; im++)
                #pragma unroll
                for (int j = 0; j < 8; j++) MMAH(acc[im][j], a_l[im], b_h[j]);
        }
    }
#undef LOAD_STAGE
    __syncthreads();   // protect smem reuse in epilogue

    uint16_t* pCh = Ch + bz * sCz;
    uint16_t* pCl = Cl ? Cl + bz * sCz : nullptr;

    if (mode == 0) {
        float* base = Cf + bz * sCz;
        #pragma unroll
        for (int im = 0; im < 2; im++) {
            int gm = m0 + wm + im * 16 + (lane >> 2);
            #pragma unroll
            for (int j = 0; j < 8; j++) {
                int gn = n0 + wn + j * 8 + 2 * (lane & 3);
                *reinterpret_cast<float2*>(base + (size_t)gm * N + gn) =
                    make_float2(acc[im][j][0], acc[im][j][1]);
                *reinterpret_cast<float2*>(base + (size_t)(gm + 8) * N + gn) =
                    make_float2(acc[im][j][2], acc[im][j][3]);
            }
        }
    } else if (mode == 1) {
        #pragma unroll
        for (int im = 0; im < 2; im++) {
            int gm = m0 + wm + im * 16 + (lane >> 2);
            #pragma unroll
            for (int j = 0; j < 8; j++) {
                int gn = n0 + wn + j * 8 + 2 * (lane & 3);
                float b0 = bias[gn], b1 = bias[gn + 1];
                uint32_t h, l;
                split2h(acc[im][j][0] + b0, acc[im][j][1] + b1, h, l);
                *reinterpret_cast<uint32_t*>(pCh + (size_t)gm * N + gn) = h;
                *reinterpret_cast<uint32_t*>(pCl + (size_t)gm * N + gn) = l;
                split2h(acc[im][j][2] + b0, acc[im][j][3] + b1, h, l);
                *reinterpret_cast<uint32_t*>(pCh + (size_t)(gm + 8) * N + gn) = h;
                *reinterpret_cast<uint32_t*>(pCl + (size_t)(gm + 8) * N + gn) = l;
            }
        }
    } else if (mode == 2) {
        float* sC = reinterpret_cast<float*>(smem);
        #pragma unroll
        for (int im = 0; im < 2; im++) {
            int rr = wm + im * 16 + (lane >> 2);
            #pragma unroll
            for (int j = 0; j < 8; j++) {
                int cc = wn + j * 8 + 2 * (lane & 3);
                sC[rr * 128 + cc]           = acc[im][j][0];
                sC[rr * 128 + cc + 1]       = acc[im][j][1];
                sC[(rr + 8) * 128 + cc]     = acc[im][j][2];
                sC[(rr + 8) * 128 + cc + 1] = acc[im][j][3];
            }
        }
        __syncthreads();
        const int nl = tid & 127;
        const int mh = tid >> 7;
        const float bv = bias ? bias[n0 + nl] : 0.f;
        const int b  = m0 >> 11;
        const int l0 = (m0 & (LL - 1)) + mh * 64;
        size_t base = ((size_t)b * DD + (n0 + nl)) * (size_t)LL + l0;
        for (int i = 0; i < 64; i += 8) {
            uint32_t w[4];
            #pragma unroll
            for (int p = 0; p < 4; p++) {
                float v0 = sC[(mh * 64 + i + 2 * p)     * 128 + nl] + bv;
                float v1 = sC[(mh * 64 + i + 2 * p + 1) * 128 + nl] + bv;
                w[p] = packh2(v0, v1);
            }
            *reinterpret_cast<uint4*>(Ch + base + i) =
                make_uint4(w[0], w[1], w[2], w[3]);
        }
    } else {
        // mode 3: E = exp(S) bf16 hi/lo planes + per-tile column sums
        float cs[8][2];
        #pragma unroll
        for (int j = 0; j < 8; j++) { cs[j][0] = 0.f; cs[j][1] = 0.f; }
        #pragma unroll
        for (int im = 0; im < 2; im++) {
            int gm = m0 + wm + im * 16 + (lane >> 2);
            #pragma unroll
            for (int j = 0; j < 8; j++) {
                int gn = n0 + wn + j * 8 + 2 * (lane & 3);
                float e0 = fast_exp(acc[im][j][0]);
                float e1 = fast_exp(acc[im][j][1]);
                float e2 = fast_exp(acc[im][j][2]);
                float e3 = fast_exp(acc[im][j][3]);
                uint32_t h, l;
                split2b(e0, e1, h, l);
                *reinterpret_cast<uint32_t*>(pCh + (size_t)gm * N + gn) = h;
                *reinterpret_cast<uint32_t*>(pCl + (size_t)gm * N + gn) = l;
                split2b(e2, e3, h, l);
                *reinterpret_cast<uint32_t*>(pCh + (size_t)(gm + 8) * N + gn) = h;
                *reinterpret_cast<uint32_t*>(pCl + (size_t)(gm + 8) * N + gn) = l;
                cs[j][0] += e0 + e2;
                cs[j][1] += e1 + e3;
            }
        }
        #pragma unroll
        for (int j = 0; j < 8; j++) {
            #pragma unroll
            for (int off = 4; off <= 16; off <<= 1) {
                cs[j][0] += __shfl_xor_sync(0xffffffffu, cs[j][0], off);
                cs[j][1] += __shfl_xor_sync(0xffffffffu, cs[j][1], off);
            }
        }
        float* sPart = reinterpret_cast<float*>(smem);
        if (lane < 4) {
            int mwarp = warp >> 1;
            #pragma unroll
            for (int j = 0; j < 8; j++) {
                int col = wn + j * 8 + 2 * (lane & 3);
                sPart[mwarp * 128 + col]     = cs[j][0];
                sPart[mwarp * 128 + col + 1] = cs[j][1];
            }
        }
        __syncthreads();
        if (tid < 128) {
            float tot = sPart[tid] + sPart[128 + tid] +
                        sPart[256 + tid] + sPart[384 + tid];
            g_pz[(size_t)blockIdx.y * BL + bz * LL + n0 + tid] = tot;
        }
    }
}

// ---------------------------------------------------------------------------
// fused fp32 -> fp16 hi/lo split for 3 arrays (blockIdx.y selects)
// ---------------------------------------------------------------------------
__global__ void __launch_bounds__(256) cvt3(
    const float* __restrict__ s0, const float* __restrict__ s1,
    const float* __restrict__ s2,
    __half* __restrict__ h0, __half* __restrict__ l0,
    __half* __restrict__ h1, __half* __restrict__ l1,
    __half* __restrict__ h2, __half* __restrict__ l2)
{
    const float* s = (blockIdx.y == 0) ? s0 : (blockIdx.y == 1) ? s1 : s2;
    __half* h = (blockIdx.y == 0) ? h0 : (blockIdx.y == 1) ? h1 : h2;
    __half* l = (blockIdx.y == 0) ? l0 : (blockIdx.y == 1) ? l1 : l2;
    size_t i = (size_t)blockIdx.x * 256 + threadIdx.x;
    float4 v = reinterpret_cast<const float4*>(s)[i];
    uint32_t ha, la, hb, lb;
    split2h(v.x, v.y, ha, la);
    split2h(v.z, v.w, hb, lb);
    reinterpret_cast<uint32_t*>(h)[2 * i + 0] = ha;
    reinterpret_cast<uint32_t*>(h)[2 * i + 1] = hb;
    reinterpret_cast<uint32_t*>(l)[2 * i + 0] = la;
    reinterpret_cast<uint32_t*>(l)[2 * i + 1] = lb;
}

// rz[b,j] = 1 / sum over 16 row-tile partials
__global__ void __launch_bounds__(256) colsum_combine()
{
    const int c = blockIdx.x * 256 + threadIdx.x;
    float z = 0.f;
    #pragma unroll
    for (int s = 0; s < 16; s++) z += g_pz[(size_t)s * BL + c];
    g_crcpz[c] = 1.f / z;
}

// P = E * rcpz (column j), fp16 hi/lo planes, 8 elems/thread
__global__ void __launch_bounds__(256) pnorm()
{
    size_t i8 = (size_t)blockIdx.x * 256 + threadIdx.x;
    size_t e0 = i8 * 8;
    int b = (int)(e0 >> 22);
    int j = (int)(e0 & (LL - 1));
    uint4 eh4 = reinterpret_cast<const uint4*>(g_Eh)[i8];
    uint4 el4 = reinterpret_cast<const uint4*>(g_El)[i8];
    float4 rz0 = *reinterpret_cast<const float4*>(&g_crcpz[b * LL + j]);
    float4 rz1 = *reinterpret_cast<const float4*>(&g_crcpz[b * LL + j + 4]);
    const float rz[8] = {rz0.x, rz0.y, rz0.z, rz0.w, rz1.x, rz1.y, rz1.z, rz1.w};
    uint32_t eh[4] = {eh4.x, eh4.y, eh4.z, eh4.w};
    uint32_t el[4] = {el4.x, el4.y, el4.z, el4.w};
    uint32_t ph[4], pl[4];
    #pragma unroll
    for (int p = 0; p < 4; p++) {
        __nv_bfloat162 hh, ll;
        memcpy(&hh, &eh[p], 4);
        memcpy(&ll, &el[p], 4);
        float v0 = (__bfloat162float(hh.x) + __bfloat162float(ll.x)) * rz[2*p];
        float v1 = (__bfloat162float(hh.y) + __bfloat162float(ll.y)) * rz[2*p+1];
        split2h(v0, v1, ph[p], pl[p]);
    }
    reinterpret_cast<uint4*>(g_Ph)[i8] = make_uint4(ph[0], ph[1], ph[2], ph[3]);
    reinterpret_cast<uint4*>(g_Pl)[i8] = make_uint4(pl[0], pl[1], pl[2], pl[3]);
}

// ---------------------------------------------------------------------------
extern "C" void kernel_launch(void* const* d_in, const int* in_sizes, int n_in,
                              void* d_out, int out_size)
{
    const float* q  = (const float*)d_in[0];
    const float* k  = (const float*)d_in[1];
    const float* v  = (const float*)d_in[2];
    const float* Wq = (const float*)d_in[3];
    const float* bq = (const float*)d_in[4];
    const float* Wk = (const float*)d_in[5];
    const float* bk = (const float*)d_in[6];
    const float* Wv = (const float*)d_in[7];
    const float* bv = (const float*)d_in[8];
    float* out = (float*)d_out;

    __half *qh, *ql, *kh, *kl, *vh, *vl;
    __half *Wqh, *Wql, *Wkh, *Wkl, *Wvh, *Wvl;
    __half *qph, *qpl, *kph, *kpl, *vpTh, *Ph, *Pl;
    __nv_bfloat16 *Eh, *El;
    cudaGetSymbolAddress((void**)&qh, g_qh);   cudaGetSymbolAddress((void**)&ql, g_ql);
    cudaGetSymbolAddress((void**)&kh, g_kh);   cudaGetSymbolAddress((void**)&kl, g_kl);
    cudaGetSymbolAddress((void**)&vh, g_vh);   cudaGetSymbolAddress((void**)&vl, g_vl);
    cudaGetSymbolAddress((void**)&Wqh, g_Wqh); cudaGetSymbolAddress((void**)&Wql, g_Wql);
    cudaGetSymbolAddress((void**)&Wkh, g_Wkh); cudaGetSymbolAddress((void**)&Wkl, g_Wkl);
    cudaGetSymbolAddress((void**)&Wvh, g_Wvh); cudaGetSymbolAddress((void**)&Wvl, g_Wvl);
    cudaGetSymbolAddress((void**)&qph, g_qph); cudaGetSymbolAddress((void**)&qpl, g_qpl);
    cudaGetSymbolAddress((void**)&kph, g_kph); cudaGetSymbolAddress((void**)&kpl, g_kpl);
    cudaGetSymbolAddress((void**)&vpTh, g_vpTh);
    cudaGetSymbolAddress((void**)&Ph, g_Ph);   cudaGetSymbolAddress((void**)&Pl, g_Pl);
    cudaGetSymbolAddress((void**)&Eh, g_Eh);   cudaGetSymbolAddress((void**)&El, g_El);

    cudaFuncSetAttribute(gemm_mma<3>, cudaFuncAttributeMaxDynamicSharedMemorySize,
                         SMEM_BYTES);
    cudaFuncSetAttribute(gemm_mma<2>, cudaFuncAttributeMaxDynamicSharedMemorySize,
                         SMEM_BYTES);

    // 1) splits (2 launches so the S-GEMM is launch #6 for ncu -s 5)
    {
        dim3 gi((BL * DD) / 1024, 3);
        cvt3<<<gi, 256>>>(q, k, v, qh, ql, kh, kl, vh, vl);
        dim3 gw((DD * DD) / 1024, 3);
        cvt3<<<gw, 256>>>(Wq, Wk, Wv, Wqh, Wql, Wkh, Wkl, Wvh, Wvl);
    }

    // 2) projections (fp16 3-term)
    {
        dim3 gp(DD / 128, BL / 128, 1);
        gemm_mma<3><<<gp, 256, SMEM_BYTES>>>(
            (uint16_t*)qh, (uint16_t*)ql, (uint16_t*)Wqh, (uint16_t*)Wql, bq,
            nullptr, (uint16_t*)qph, (uint16_t*)qpl, DD, DD, 0, 0, 0, 1);
        gemm_mma<3><<<gp, 256, SMEM_BYTES>>>(
            (uint16_t*)kh, (uint16_t*)kl, (uint16_t*)Wkh, (uint16_t*)Wkl, bk,
            nullptr, (uint16_t*)kph, (uint16_t*)kpl, DD, DD, 0, 0, 0, 1);
        gemm_mma<3><<<gp, 256, SMEM_BYTES>>>(
            (uint16_t*)vh, (uint16_t*)vl, (uint16_t*)Wvh, (uint16_t*)Wvl, bv,
            nullptr, (uint16_t*)vpTh, nullptr, DD, DD, 0, 0, 0, 2);
    }

    // 3) E[b] = exp(qp kp^T) bf16 planes + colsums  (launch #6 -> profiled)
    {
        dim3 gs(LL / 128, LL / 128, BB);
        gemm_mma<3><<<gs, 256, SMEM_BYTES>>>(
            (uint16_t*)qph, (uint16_t*)qpl, (uint16_t*)kph, (uint16_t*)kpl,
            nullptr, nullptr, (uint16_t*)Eh, (uint16_t*)El,
            LL, DD, (size_t)LL * DD, (size_t)LL * DD, (size_t)LL * LL, 3);
    }

    // 4) rcpz; P = E * rcpz (fp16 pair)
    colsum_combine<<<BL / 256, 256>>>();
    pnorm<<<(unsigned)((size_t)BB * LL * LL / (8 * 256)), 256>>>();

    // 5) out[b] = P[b] @ vpT[b]^T  (fp16 2-term)
    {
        dim3 go(DD / 128, LL / 128, BB);
        gemm_mma<2><<<go, 256, SMEM_BYTES>>>(
            (uint16_t*)Ph, (uint16_t*)Pl, (uint16_t*)vpTh, nullptr, nullptr,
            out, nullptr, nullptr,
            DD, LL, (size_t)LL * LL, (size_t)DD * LL, (size_t)LL * DD, 0);
    }
}

// round 7
// speedup vs baseline: 1.0571x; 1.0571x over previous
#include <cuda_runtime.h>
#include <cuda_bf16.h>
#include <cstdint>
#include <math.h>

#define BB 8
#define LL 2048
#define DD 512
#define BL (BB*LL)

// ---------------------------------------------------------------------------
// Device scratch
// ---------------------------------------------------------------------------
__device__ __align__(256) __nv_bfloat16 g_Eh[(size_t)BB*LL*LL];
__device__ __align__(256) __nv_bfloat16 g_El[(size_t)BB*LL*LL];
__device__ __align__(256) __nv_bfloat16 g_qh[BL*DD], g_ql[BL*DD];
__device__ __align__(256) __nv_bfloat16 g_kh[BL*DD], g_kl[BL*DD];
__device__ __align__(256) __nv_bfloat16 g_vh[BL*DD], g_vl[BL*DD];
__device__ __align__(256) __nv_bfloat16 g_Wqh[DD*DD], g_Wql[DD*DD];
__device__ __align__(256) __nv_bfloat16 g_Wkh[DD*DD], g_Wkl[DD*DD];
__device__ __align__(256) __nv_bfloat16 g_Wvh[DD*DD], g_Wvl[DD*DD];
__device__ __align__(256) __nv_bfloat16 g_qph[BL*DD], g_qpl[BL*DD];
__device__ __align__(256) __nv_bfloat16 g_kph[BL*DD], g_kpl[BL*DD];
__device__ __align__(256) __nv_bfloat16 g_vpTh[BL*DD], g_vpTl[BL*DD]; // [B][D][L]
__device__ __align__(256) float g_crcpz[BL];
__device__ __align__(256) float g_pz[16*BL];

// ---------------------------------------------------------------------------
// Portable PTX helpers (sm_80+)
// ---------------------------------------------------------------------------
__device__ __forceinline__ uint32_t smem_u32(const void* p) {
    uint32_t a;
    asm("{ .reg .u64 t; cvta.to.shared.u64 t, %1; cvt.u32.u64 %0, t; }"
        : "=r"(a) : "l"(p));
    return a;
}

#define CP16(dst, src) \
    asm volatile("cp.async.cg.shared.global [%0], [%1], 16;" \
                 :: "r"(dst), "l"(src) : "memory")
#define CP_COMMIT() asm volatile("cp.async.commit_group;" ::: "memory")
#define CP_WAIT1()  asm volatile("cp.async.wait_group 1;" ::: "memory")

#define LDSM4(r0, r1, r2, r3, addr) \
    asm volatile("ldmatrix.sync.aligned.m8n8.x4.shared.b16 {%0,%1,%2,%3}, [%4];" \
                 : "=r"(r0), "=r"(r1), "=r"(r2), "=r"(r3) : "r"(addr))

#define MMA(d, a, b) \
    asm volatile("mma.sync.aligned.m16n8k16.row.col.f32.bf16.bf16.f32 " \
                 "{%0,%1,%2,%3}, {%4,%5,%6,%7}, {%8,%9}, {%0,%1,%2,%3};" \
                 : "+f"((d)[0]), "+f"((d)[1]), "+f"((d)[2]), "+f"((d)[3]) \
                 : "r"((a)[0]), "r"((a)[1]), "r"((a)[2]), "r"((a)[3]), \
                   "r"((b)[0]), "r"((b)[1]))

__device__ __forceinline__ void split2(float v0, float v1,
                                       uint32_t& h, uint32_t& l) {
    __nv_bfloat16 h0 = __float2bfloat16(v0);
    __nv_bfloat16 h1 = __float2bfloat16(v1);
    __nv_bfloat162 th; th.x = h0; th.y = h1;
    memcpy(&h, &th, 4);
    __nv_bfloat162 tl;
    tl.x = __float2bfloat16(v0 - __bfloat162float(h0));
    tl.y = __float2bfloat16(v1 - __bfloat162float(h1));
    memcpy(&l, &tl, 4);
}

// Fast exp on the FMA pipe (rel err ~2e-6)
__device__ __forceinline__ float fast_exp(float x) {
    float y = x * 1.4426950408889634f;
    float t = y + 12582912.f;
    int   n = __float_as_int(t) - 0x4B400000;
    t -= 12582912.f;
    float f = y - t;
    float p = 1.3333558146e-3f;
    p = fmaf(p, f, 9.6181291076e-3f);
    p = fmaf(p, f, 5.5504108664e-2f);
    p = fmaf(p, f, 2.4022650696e-1f);
    p = fmaf(p, f, 6.9314718056e-1f);
    p = fmaf(p, f, 1.0f);
    return __int_as_float(__float_as_int(p) + (n << 23));
}

// smem: 3 stages x 4 planes x 8KB = 96KB
#define PL_AH 0
#define PL_AL 8192
#define PL_BH 16384
#define PL_BL 24576
#define STAGE_BYTES 32768
#define SMEM_BYTES 98304

__device__ __forceinline__ uint32_t swz(int r, int kc) {
    return (uint32_t)(r * 64 + ((kc ^ ((r >> 1) & 3)) << 4));
}

// ---------------------------------------------------------------------------
// NT GEMM, bf16x3 split precision via mma.sync.m16n8k16.
// 3-stage cp.async ring, lookahead 2, single __syncthreads per k-iter.
// mode 0: Cf fp32 row-major.
// mode 1: Ch/Cl bf16 planes row-major (+bias).
// mode 2: Ch/Cl bf16 planes transposed per batch -> [b][n][m%LL] (+bias).
// mode 3: Ch/Cl = exp(C) bf16 planes row-major + per-tile colsums -> g_pz.
// ---------------------------------------------------------------------------
__global__ void __launch_bounds__(256, 2) gemm_mma(
    const __nv_bfloat16* __restrict__ Ah, const __nv_bfloat16* __restrict__ Al,
    const __nv_bfloat16* __restrict__ Bh, const __nv_bfloat16* __restrict__ Bl,
    const float* __restrict__ bias,
    float* __restrict__ Cf,
    __nv_bfloat16* __restrict__ Ch, __nv_bfloat16* __restrict__ Cl,
    int N, int K,
    size_t sAz, size_t sBz, size_t sCz,
    int mode)
{
    extern __shared__ char smem[];
    const uint32_t sbase = smem_u32(smem);
    const int tid  = threadIdx.x;
    const int lane = tid & 31;
    const int warp = tid >> 5;
    const int wm = (warp >> 1) * 32;
    const int wn = (warp & 1) * 64;
    const int m0 = blockIdx.y * 128, n0 = blockIdx.x * 128, bz = blockIdx.z;

    // hoisted cp.async addressing (stage-invariant parts)
    uint32_t dOff[2];
    size_t   gOff[2];
    #pragma unroll
    for (int i = 0; i < 2; i++) {
        int idx = tid + i * 256;
        int r = idx >> 2, c = idx & 3;
        dOff[i] = swz(r, c);
        gOff[i] = (size_t)r * K + c * 8;
    }
    const __nv_bfloat16* pAh = Ah + bz * sAz + (size_t)m0 * K;
    const __nv_bfloat16* pAl = Al + bz * sAz + (size_t)m0 * K;
    const __nv_bfloat16* pBh = Bh + bz * sBz + (size_t)n0 * K;
    const __nv_bfloat16* pBl = Bl + bz * sBz + (size_t)n0 * K;

    float acc[2][8][4];
    #pragma unroll
    for (int i = 0; i < 2; i++)
        #pragma unroll
        for (int j = 0; j < 8; j++)
            #pragma unroll
            for (int c = 0; c < 4; c++) acc[i][j][c] = 0.f;

#define LOAD_STAGE(slot, kt) do { \
    uint32_t so_ = sbase + (uint32_t)(slot) * STAGE_BYTES; \
    size_t ko_ = (size_t)(kt) * 32; \
    _Pragma("unroll") \
    for (int i_ = 0; i_ < 2; i_++) { \
        uint32_t d_ = so_ + dOff[i_]; \
        size_t g_ = gOff[i_] + ko_; \
        CP16(d_ + PL_AH, pAh + g_); \
        CP16(d_ + PL_AL, pAl + g_); \
        CP16(d_ + PL_BH, pBh + g_); \
        CP16(d_ + PL_BL, pBl + g_); \
    } \
} while (0)

    const int nk = K >> 5;       // >= 16 always
    LOAD_STAGE(0, 0); CP_COMMIT();
    LOAD_STAGE(1, 1); CP_COMMIT();

    int slot = 0, nslot = 2;
    for (int kt = 0; kt < nk; kt++) {
        CP_WAIT1();
        __syncthreads();
        if (kt + 2 < nk) LOAD_STAGE(nslot, kt + 2);
        CP_COMMIT();

        const uint32_t so = sbase + (uint32_t)slot * STAGE_BYTES;
        #pragma unroll
        for (int ks = 0; ks < 2; ks++) {
            uint32_t a_h[2][4], a_l[2][4];
            const int kc = ks * 2 + (lane >> 4);
            #pragma unroll
            for (int im = 0; im < 2; im++) {
                int rr = wm + im * 16 + (lane & 7) + ((lane >> 3) & 1) * 8;
                uint32_t ad = so + swz(rr, kc);
                LDSM4(a_h[im][0], a_h[im][1], a_h[im][2], a_h[im][3], ad + PL_AH);
                LDSM4(a_l[im][0], a_l[im][1], a_l[im][2], a_l[im][3], ad + PL_AL);
            }
            uint32_t b_h[8][2], b_l[8][2];
            #pragma unroll
            for (int j4 = 0; j4 < 4; j4++) {
                int rr = wn + j4 * 16 + (lane & 7) + ((lane >> 3) & 1) * 8;
                uint32_t bd = so + swz(rr, kc);
                LDSM4(b_h[2*j4][0], b_h[2*j4+1][0], b_h[2*j4][1], b_h[2*j4+1][1],
                      bd + PL_BH);
                LDSM4(b_l[2*j4][0], b_l[2*j4+1][0], b_l[2*j4][1], b_l[2*j4+1][1],
                      bd + PL_BL);
            }
            #pragma unroll
            for (int im = 0; im < 2; im++)
                #pragma unroll
                for (int j = 0; j < 8; j++) MMA(acc[im][j], a_h[im], b_h[j]);
            #pragma unroll
            for (int im = 0; im < 2; im++)
                #pragma unroll
                for (int j = 0; j < 8; j++) MMA(acc[im][j], a_h[im], b_l[j]);
            #pragma unroll
            for (int im = 0; im < 2; im++)
                #pragma unroll
                for (int j = 0; j < 8; j++) MMA(acc[im][j], a_l[im], b_h[j]);
        }
        slot = (slot == 2) ? 0 : slot + 1;
        nslot = (nslot == 2) ? 0 : nslot + 1;
    }
#undef LOAD_STAGE
    __syncthreads();   // smem reused by epilogues

    __nv_bfloat16* pCh = Ch + bz * sCz;
    __nv_bfloat16* pCl = Cl ? Cl + bz * sCz : nullptr;

    if (mode == 0) {
        float* base = Cf + bz * sCz;
        #pragma unroll
        for (int im = 0; im < 2; im++) {
            int gm = m0 + wm + im * 16 + (lane >> 2);
            #pragma unroll
            for (int j = 0; j < 8; j++) {
                int gn = n0 + wn + j * 8 + 2 * (lane & 3);
                *reinterpret_cast<float2*>(base + (size_t)gm * N + gn) =
                    make_float2(acc[im][j][0], acc[im][j][1]);
                *reinterpret_cast<float2*>(base + (size_t)(gm + 8) * N + gn) =
                    make_float2(acc[im][j][2], acc[im][j][3]);
            }
        }
    } else if (mode == 1) {
        #pragma unroll
        for (int im = 0; im < 2; im++) {
            int gm = m0 + wm + im * 16 + (lane >> 2);
            #pragma unroll
            for (int j = 0; j < 8; j++) {
                int gn = n0 + wn + j * 8 + 2 * (lane & 3);
                float b0 = bias[gn], b1 = bias[gn + 1];
                uint32_t h, l;
                split2(acc[im][j][0] + b0, acc[im][j][1] + b1, h, l);
                *reinterpret_cast<uint32_t*>(pCh + (size_t)gm * N + gn) = h;
                *reinterpret_cast<uint32_t*>(pCl + (size_t)gm * N + gn) = l;
                split2(acc[im][j][2] + b0, acc[im][j][3] + b1, h, l);
                *reinterpret_cast<uint32_t*>(pCh + (size_t)(gm + 8) * N + gn) = h;
                *reinterpret_cast<uint32_t*>(pCl + (size_t)(gm + 8) * N + gn) = l;
            }
        }
    } else if (mode == 2) {
        float* sC = reinterpret_cast<float*>(smem);
        #pragma unroll
        for (int im = 0; im < 2; im++) {
            int rr = wm + im * 16 + (lane >> 2);
            #pragma unroll
            for (int j = 0; j < 8; j++) {
                int cc = wn + j * 8 + 2 * (lane & 3);
                sC[rr * 128 + cc]           = acc[im][j][0];
                sC[rr * 128 + cc + 1]       = acc[im][j][1];
                sC[(rr + 8) * 128 + cc]     = acc[im][j][2];
                sC[(rr + 8) * 128 + cc + 1] = acc[im][j][3];
            }
        }
        __syncthreads();
        const int nl = tid & 127;
        const int mh = tid >> 7;
        const float bv = bias ? bias[n0 + nl] : 0.f;
        const int b  = m0 >> 11;
        const int l0 = (m0 & (LL - 1)) + mh * 64;
        size_t base = ((size_t)b * DD + (n0 + nl)) * (size_t)LL + l0;
        for (int i = 0; i < 64; i += 8) {
            uint32_t hr[4], lr[4];
            #pragma unroll
            for (int p = 0; p < 4; p++) {
                float v0 = sC[(mh * 64 + i + 2 * p)     * 128 + nl] + bv;
                float v1 = sC[(mh * 64 + i + 2 * p + 1) * 128 + nl] + bv;
                split2(v0, v1, hr[p], lr[p]);
            }
            *reinterpret_cast<uint4*>(Ch + base + i) =
                make_uint4(hr[0], hr[1], hr[2], hr[3]);
            *reinterpret_cast<uint4*>(Cl + base + i) =
                make_uint4(lr[0], lr[1], lr[2], lr[3]);
        }
    } else {
        // mode 3: E = exp(S) bf16 hi/lo planes + per-tile column sums
        float cs[8][2];
        #pragma unroll
        for (int j = 0; j < 8; j++) { cs[j][0] = 0.f; cs[j][1] = 0.f; }
        #pragma unroll
        for (int im = 0; im < 2; im++) {
            int gm = m0 + wm + im * 16 + (lane >> 2);
            #pragma unroll
            for (int j = 0; j < 8; j++) {
                int gn = n0 + wn + j * 8 + 2 * (lane & 3);
                float e0 = fast_exp(acc[im][j][0]);
                float e1 = fast_exp(acc[im][j][1]);
                float e2 = fast_exp(acc[im][j][2]);
                float e3 = fast_exp(acc[im][j][3]);
                uint32_t h, l;
                split2(e0, e1, h, l);
                *reinterpret_cast<uint32_t*>(pCh + (size_t)gm * N + gn) = h;
                *reinterpret_cast<uint32_t*>(pCl + (size_t)gm * N + gn) = l;
                split2(e2, e3, h, l);
                *reinterpret_cast<uint32_t*>(pCh + (size_t)(gm + 8) * N + gn) = h;
                *reinterpret_cast<uint32_t*>(pCl + (size_t)(gm + 8) * N + gn) = l;
                cs[j][0] += e0 + e2;
                cs[j][1] += e1 + e3;
            }
        }
        #pragma unroll
        for (int j = 0; j < 8; j++) {
            #pragma unroll
            for (int off = 4; off <= 16; off <<= 1) {
                cs[j][0] += __shfl_xor_sync(0xffffffffu, cs[j][0], off);
                cs[j][1] += __shfl_xor_sync(0xffffffffu, cs[j][1], off);
            }
        }
        float* sPart = reinterpret_cast<float*>(smem);
        if (lane < 4) {
            int mwarp = warp >> 1;
            #pragma unroll
            for (int j = 0; j < 8; j++) {
                int col = wn + j * 8 + 2 * (lane & 3);
                sPart[mwarp * 128 + col]     = cs[j][0];
                sPart[mwarp * 128 + col + 1] = cs[j][1];
            }
        }
        __syncthreads();
        if (tid < 128) {
            float tot = sPart[tid] + sPart[128 + tid] +
                        sPart[256 + tid] + sPart[384 + tid];
            g_pz[(size_t)blockIdx.y * BL + bz * LL + n0 + tid] = tot;
        }
    }
}

// ---------------------------------------------------------------------------
// fused fp32 -> bf16 hi/lo split for 3 arrays (blockIdx.y selects)
// ---------------------------------------------------------------------------
__global__ void __launch_bounds__(256) cvt3(
    const float* __restrict__ s0, const float* __restrict__ s1,
    const float* __restrict__ s2,
    __nv_bfloat16* __restrict__ h0, __nv_bfloat16* __restrict__ l0,
    __nv_bfloat16* __restrict__ h1, __nv_bfloat16* __restrict__ l1,
    __nv_bfloat16* __restrict__ h2, __nv_bfloat16* __restrict__ l2)
{
    const float* s = (blockIdx.y == 0) ? s0 : (blockIdx.y == 1) ? s1 : s2;
    __nv_bfloat16* h = (blockIdx.y == 0) ? h0 : (blockIdx.y == 1) ? h1 : h2;
    __nv_bfloat16* l = (blockIdx.y == 0) ? l0 : (blockIdx.y == 1) ? l1 : l2;
    size_t i = (size_t)blockIdx.x * 256 + threadIdx.x;
    float4 v = reinterpret_cast<const float4*>(s)[i];
    uint32_t ha, la, hb, lb;
    split2(v.x, v.y, ha, la);
    split2(v.z, v.w, hb, lb);
    reinterpret_cast<uint32_t*>(h)[2 * i + 0] = ha;
    reinterpret_cast<uint32_t*>(h)[2 * i + 1] = hb;
    reinterpret_cast<uint32_t*>(l)[2 * i + 0] = la;
    reinterpret_cast<uint32_t*>(l)[2 * i + 1] = lb;
}

// rz[b,j] = 1 / sum over 16 row-tile partials
__global__ void __launch_bounds__(256) colsum_combine()
{
    const int c = blockIdx.x * 256 + threadIdx.x;
    float z = 0.f;
    #pragma unroll
    for (int s = 0; s < 16; s++) z += g_pz[(size_t)s * BL + c];
    g_crcpz[c] = 1.f / z;
}

// vpT[b][d][l] *= rz[b][l], in place on bf16 hi/lo planes
__global__ void __launch_bounds__(256) scale_vpT()
{
    size_t idx = (size_t)blockIdx.x * 256 + threadIdx.x;
    size_t e0  = idx * 8;
    int l   = (int)(e0 & (LL - 1));
    int row = (int)(e0 >> 11);
    int b   = row >> 9;
    uint4 hv = reinterpret_cast<uint4*>(g_vpTh)[idx];
    uint4 lv = reinterpret_cast<uint4*>(g_vpTl)[idx];
    const float* rz = &g_crcpz[b * LL + l];
    uint32_t hw[4] = {hv.x, hv.y, hv.z, hv.w};
    uint32_t lw[4] = {lv.x, lv.y, lv.z, lv.w};
    #pragma unroll
    for (int p = 0; p < 4; p++) {
        __nv_bfloat162 hh, ll;
        memcpy(&hh, &hw[p], 4);
        memcpy(&ll, &lw[p], 4);
        float v0 = (__bfloat162float(hh.x) + __bfloat162float(ll.x)) * rz[2 * p];
        float v1 = (__bfloat162float(hh.y) + __bfloat162float(ll.y)) * rz[2 * p + 1];
        split2(v0, v1, hw[p], lw[p]);
    }
    reinterpret_cast<uint4*>(g_vpTh)[idx] = make_uint4(hw[0], hw[1], hw[2], hw[3]);
    reinterpret_cast<uint4*>(g_vpTl)[idx] = make_uint4(lw[0], lw[1], lw[2], lw[3]);
}

// ---------------------------------------------------------------------------
extern "C" void kernel_launch(void* const* d_in, const int* in_sizes, int n_in,
                              void* d_out, int out_size)
{
    const float* q  = (const float*)d_in[0];
    const float* k  = (const float*)d_in[1];
    const float* v  = (const float*)d_in[2];
    const float* Wq = (const float*)d_in[3];
    const float* bq = (const float*)d_in[4];
    const float* Wk = (const float*)d_in[5];
    const float* bk = (const float*)d_in[6];
    const float* Wv = (const float*)d_in[7];
    const float* bv = (const float*)d_in[8];
    float* out = (float*)d_out;

    __nv_bfloat16 *qh, *ql, *kh, *kl, *vh, *vl;
    __nv_bfloat16 *Wqh, *Wql, *Wkh, *Wkl, *Wvh, *Wvl;
    __nv_bfloat16 *qph, *qpl, *kph, *kpl, *vpTh, *vpTl, *Eh, *El;
    cudaGetSymbolAddress((void**)&qh, g_qh);   cudaGetSymbolAddress((void**)&ql, g_ql);
    cudaGetSymbolAddress((void**)&kh, g_kh);   cudaGetSymbolAddress((void**)&kl, g_kl);
    cudaGetSymbolAddress((void**)&vh, g_vh);   cudaGetSymbolAddress((void**)&vl, g_vl);
    cudaGetSymbolAddress((void**)&Wqh, g_Wqh); cudaGetSymbolAddress((void**)&Wql, g_Wql);
    cudaGetSymbolAddress((void**)&Wkh, g_Wkh); cudaGetSymbolAddress((void**)&Wkl, g_Wkl);
    cudaGetSymbolAddress((void**)&Wvh, g_Wvh); cudaGetSymbolAddress((void**)&Wvl, g_Wvl);
    cudaGetSymbolAddress((void**)&qph, g_qph); cudaGetSymbolAddress((void**)&qpl, g_qpl);
    cudaGetSymbolAddress((void**)&kph, g_kph); cudaGetSymbolAddress((void**)&kpl, g_kpl);
    cudaGetSymbolAddress((void**)&vpTh, g_vpTh); cudaGetSymbolAddress((void**)&vpTl, g_vpTl);
    cudaGetSymbolAddress((void**)&Eh, g_Eh);   cudaGetSymbolAddress((void**)&El, g_El);

    cudaFuncSetAttribute(gemm_mma, cudaFuncAttributeMaxDynamicSharedMemorySize,
                         SMEM_BYTES);

    // 1) splits (2 launches so the S-GEMM is launch #6 for ncu -s 5)
    {
        dim3 gi((BL * DD) / 1024, 3);
        cvt3<<<gi, 256>>>(q, k, v, qh, ql, kh, kl, vh, vl);
        dim3 gw((DD * DD) / 1024, 3);
        cvt3<<<gw, 256>>>(Wq, Wk, Wv, Wqh, Wql, Wkh, Wkl, Wvh, Wvl);
    }

    // 2) projections
    {
        dim3 gp(DD / 128, BL / 128, 1);
        gemm_mma<<<gp, 256, SMEM_BYTES>>>(qh, ql, Wqh, Wql, bq,
                                          nullptr, qph, qpl, DD, DD, 0, 0, 0, 1);
        gemm_mma<<<gp, 256, SMEM_BYTES>>>(kh, kl, Wkh, Wkl, bk,
                                          nullptr, kph, kpl, DD, DD, 0, 0, 0, 1);
        gemm_mma<<<gp, 256, SMEM_BYTES>>>(vh, vl, Wvh, Wvl, bv,
                                          nullptr, vpTh, vpTl, DD, DD, 0, 0, 0, 2);
    }

    // 3) E[b] = exp(qp kp^T) bf16 planes + colsums (launch #6 -> profiled)
    {
        dim3 gs(LL / 128, LL / 128, BB);
        gemm_mma<<<gs, 256, SMEM_BYTES>>>(qph, qpl, kph, kpl, nullptr,
                                          nullptr, Eh, El,
                                          LL, DD,
                                          (size_t)LL * DD, (size_t)LL * DD,
                                          (size_t)LL * LL, 3);
    }

    // 4) rz = 1/colsum; fold into vpT
    colsum_combine<<<BL / 256, 256>>>();
    scale_vpT<<<(BL * DD) / (8 * 256), 256>>>();

    // 5) out[b] = E[b] @ vpT'[b]^T
    {
        dim3 go(DD / 128, LL / 128, BB);
        gemm_mma<<<go, 256, SMEM_BYTES>>>(Eh, El, vpTh, vpTl, nullptr,
                                          out, nullptr, nullptr,
                                          DD, LL,
                                          (size_t)LL * LL, (size_t)DD * LL,
                                          (size_t)LL * DD, 0);
    }
}

// round 8
// speedup vs baseline: 1.1908x; 1.1264x over previous
#include <cuda_runtime.h>
#include <cuda_fp16.h>
#include <cstdint>
#include <math.h>

#define BB 8
#define LL 2048
#define DD 512
#define BL (BB*LL)

// ---------------------------------------------------------------------------
// Device scratch
// ---------------------------------------------------------------------------
__device__ __align__(256) __half g_Eh[(size_t)BB*LL*LL];  // E' = exp(S)*2^-26 hi
__device__ __align__(256) __half g_El[(size_t)BB*LL*LL];  // E' lo
__device__ __align__(256) __half g_qh[BL*DD], g_ql[BL*DD];
__device__ __align__(256) __half g_kh[BL*DD], g_kl[BL*DD];
__device__ __align__(256) __half g_vh[BL*DD], g_vl[BL*DD];
__device__ __align__(256) __half g_Wqh[DD*DD], g_Wql[DD*DD];
__device__ __align__(256) __half g_Wkh[DD*DD], g_Wkl[DD*DD];
__device__ __align__(256) __half g_Wvh[DD*DD], g_Wvl[DD*DD];
__device__ __align__(256) __half g_qph[BL*DD], g_qpl[BL*DD];
__device__ __align__(256) __half g_kph[BL*DD], g_kpl[BL*DD];
__device__ __align__(256) __half g_vpTh[BL*DD];           // [B][D][L] single plane
__device__ __align__(256) float g_crcpz[BL];
__device__ __align__(256) float g_pz[16*BL];

// ---------------------------------------------------------------------------
// Portable PTX helpers (sm_80+)
// ---------------------------------------------------------------------------
__device__ __forceinline__ uint32_t smem_u32(const void* p) {
    uint32_t a;
    asm("{ .reg .u64 t; cvta.to.shared.u64 t, %1; cvt.u32.u64 %0, t; }"
        : "=r"(a) : "l"(p));
    return a;
}

#define CP16(dst, src) \
    asm volatile("cp.async.cg.shared.global [%0], [%1], 16;" \
                 :: "r"(dst), "l"(src) : "memory")
#define CP_COMMIT() asm volatile("cp.async.commit_group;" ::: "memory")
#define CP_WAIT1()  asm volatile("cp.async.wait_group 1;" ::: "memory")

#define LDSM4(r0, r1, r2, r3, addr) \
    asm volatile("ldmatrix.sync.aligned.m8n8.x4.shared.b16 {%0,%1,%2,%3}, [%4];" \
                 : "=r"(r0), "=r"(r1), "=r"(r2), "=r"(r3) : "r"(addr))

#define MMAH(d, a, b) \
    asm volatile("mma.sync.aligned.m16n8k16.row.col.f32.f16.f16.f32 " \
                 "{%0,%1,%2,%3}, {%4,%5,%6,%7}, {%8,%9}, {%0,%1,%2,%3};" \
                 : "+f"((d)[0]), "+f"((d)[1]), "+f"((d)[2]), "+f"((d)[3]) \
                 : "r"((a)[0]), "r"((a)[1]), "r"((a)[2]), "r"((a)[3]), \
                   "r"((b)[0]), "r"((b)[1]))

__device__ __forceinline__ uint32_t packh2(float a, float b) {
    __half2 t = __floats2half2_rn(a, b);
    uint32_t u; memcpy(&u, &t, 4); return u;
}
__device__ __forceinline__ void split2h(float v0, float v1,
                                        uint32_t& h, uint32_t& l) {
    float h0 = __half2float(__float2half_rn(v0));
    float h1 = __half2float(__float2half_rn(v1));
    h = packh2(v0, v1);
    l = packh2(v0 - h0, v1 - h1);
}

// Fast exp * 2^-26 on the FMA pipe (rel err ~2e-6), clamped for fp16 storage
__device__ __forceinline__ float fast_exp_s26(float x) {
    float y = x * 1.4426950408889634f;
    float t = y + 12582912.f;
    int   n = __float_as_int(t) - 0x4B400000;
    t -= 12582912.f;
    float f = y - t;
    float p = 1.3333558146e-3f;
    p = fmaf(p, f, 9.6181291076e-3f);
    p = fmaf(p, f, 5.5504108664e-2f);
    p = fmaf(p, f, 2.4022650696e-1f);
    p = fmaf(p, f, 6.9314718056e-1f);
    p = fmaf(p, f, 1.0f);
    float e = __int_as_float(__float_as_int(p) + ((n - 26) << 23));
    return fminf(e, 60000.f);
}

// smem: 3 stages x 4 planes x 8KB = 96KB
#define PL_AH 0
#define PL_AL 8192
#define PL_BH 16384
#define PL_BL 24576
#define STAGE_BYTES 32768
#define SMEM_BYTES 98304

__device__ __forceinline__ uint32_t swz(int r, int kc) {
    return (uint32_t)(r * 64 + ((kc ^ ((r >> 1) & 3)) << 4));
}

// ---------------------------------------------------------------------------
// NT GEMM, fp16 split precision, mma.sync.m16n8k16, 3-stage cp.async ring.
// TERMS=3: Ah*Bh + Ah*Bl + Al*Bh.  TERMS=2: Ah*Bh + Al*Bh (no Bl).
// mode 0: Cf fp32 row-major.
// mode 1: Ch/Cl fp16 planes row-major (+bias).
// mode 2: Ch fp16 SINGLE plane transposed -> [b][n][m%LL] (+bias).
// mode 3: Ch/Cl = exp(C)*2^-26 fp16 planes row-major + per-tile colsums.
// ---------------------------------------------------------------------------
template<int TERMS>
__global__ void __launch_bounds__(256, 2) gemm_mma(
    const __half* __restrict__ Ah, const __half* __restrict__ Al,
    const __half* __restrict__ Bh, const __half* __restrict__ Bl,
    const float* __restrict__ bias,
    float* __restrict__ Cf,
    __half* __restrict__ Ch, __half* __restrict__ Cl,
    int N, int K,
    size_t sAz, size_t sBz, size_t sCz,
    int mode)
{
    extern __shared__ char smem[];
    const uint32_t sbase = smem_u32(smem);
    const int tid  = threadIdx.x;
    const int lane = tid & 31;
    const int warp = tid >> 5;
    const int wm = (warp >> 1) * 32;
    const int wn = (warp & 1) * 64;
    const int m0 = blockIdx.y * 128, n0 = blockIdx.x * 128, bz = blockIdx.z;

    // hoisted cp.async addressing
    uint32_t dOff[2];
    size_t   gOff[2];
    #pragma unroll
    for (int i = 0; i < 2; i++) {
        int idx = tid + i * 256;
        int r = idx >> 2, c = idx & 3;
        dOff[i] = swz(r, c);
        gOff[i] = (size_t)r * K + c * 8;
    }
    // hoisted ldmatrix swizzle offsets (per-warp constants)
    uint32_t offA[2][2], offB[2][4];
    #pragma unroll
    for (int ks = 0; ks < 2; ks++) {
        int kc = ks * 2 + (lane >> 4);
        int rbase = (lane & 7) + ((lane >> 3) & 1) * 8;
        #pragma unroll
        for (int im = 0; im < 2; im++)
            offA[ks][im] = swz(wm + im * 16 + rbase, kc);
        #pragma unroll
        for (int j4 = 0; j4 < 4; j4++)
            offB[ks][j4] = swz(wn + j4 * 16 + rbase, kc);
    }

    const __half* pAh = Ah + bz * sAz + (size_t)m0 * K;
    const __half* pAl = Al + bz * sAz + (size_t)m0 * K;
    const __half* pBh = Bh + bz * sBz + (size_t)n0 * K;
    const __half* pBl = (TERMS == 3) ? Bl + bz * sBz + (size_t)n0 * K : nullptr;

    float acc[2][8][4];
    #pragma unroll
    for (int i = 0; i < 2; i++)
        #pragma unroll
        for (int j = 0; j < 8; j++)
            #pragma unroll
            for (int c = 0; c < 4; c++) acc[i][j][c] = 0.f;

#define LOAD_STAGE(slot, kt) do { \
    uint32_t so_ = sbase + (uint32_t)(slot) * STAGE_BYTES; \
    size_t ko_ = (size_t)(kt) * 32; \
    _Pragma("unroll") \
    for (int i_ = 0; i_ < 2; i_++) { \
        uint32_t d_ = so_ + dOff[i_]; \
        size_t g_ = gOff[i_] + ko_; \
        CP16(d_ + PL_AH, pAh + g_); \
        CP16(d_ + PL_AL, pAl + g_); \
        CP16(d_ + PL_BH, pBh + g_); \
        if (TERMS == 3) CP16(d_ + PL_BL, pBl + g_); \
    } \
} while (0)

    const int nk = K >> 5;
    LOAD_STAGE(0, 0); CP_COMMIT();
    LOAD_STAGE(1, 1); CP_COMMIT();

    int slot = 0, nslot = 2;
    for (int kt = 0; kt < nk; kt++) {
        CP_WAIT1();
        __syncthreads();
        if (kt + 2 < nk) LOAD_STAGE(nslot, kt + 2);
        CP_COMMIT();

        const uint32_t so = sbase + (uint32_t)slot * STAGE_BYTES;
        #pragma unroll
        for (int ks = 0; ks < 2; ks++) {
            uint32_t a_h[2][4], a_l[2][4];
            #pragma unroll
            for (int im = 0; im < 2; im++) {
                uint32_t ad = so + offA[ks][im];
                LDSM4(a_h[im][0], a_h[im][1], a_h[im][2], a_h[im][3], ad + PL_AH);
                LDSM4(a_l[im][0], a_l[im][1], a_l[im][2], a_l[im][3], ad + PL_AL);
            }
            uint32_t b_h[8][2], b_l[8][2];
            #pragma unroll
            for (int j4 = 0; j4 < 4; j4++) {
                uint32_t bd = so + offB[ks][j4];
                LDSM4(b_h[2*j4][0], b_h[2*j4+1][0], b_h[2*j4][1], b_h[2*j4+1][1],
                      bd + PL_BH);
                if (TERMS == 3)
                    LDSM4(b_l[2*j4][0], b_l[2*j4+1][0], b_l[2*j4][1], b_l[2*j4+1][1],
                          bd + PL_BL);
            }
            #pragma unroll
            for (int im = 0; im < 2; im++)
                #pragma unroll
                for (int j = 0; j < 8; j++) MMAH(acc[im][j], a_h[im], b_h[j]);
            if (TERMS == 3) {
                #pragma unroll
                for (int im = 0; im < 2; im++)
                    #pragma unroll
                    for (int j = 0; j < 8; j++) MMAH(acc[im][j], a_h[im], b_l[j]);
            }
            #pragma unroll
            for (int im = 0; im < 2; im++)
                #pragma unroll
                for (int j = 0; j < 8; j++) MMAH(acc[im][j], a_l[im], b_h[j]);
        }
        slot = (slot == 2) ? 0 : slot + 1;
        nslot = (nslot == 2) ? 0 : nslot + 1;
    }
#undef LOAD_STAGE
    __syncthreads();

    __half* pCh = Ch + bz * sCz;
    __half* pCl = Cl ? Cl + bz * sCz : nullptr;

    if (mode == 0) {
        float* base = Cf + bz * sCz;
        #pragma unroll
        for (int im = 0; im < 2; im++) {
            int gm = m0 + wm + im * 16 + (lane >> 2);
            #pragma unroll
            for (int j = 0; j < 8; j++) {
                int gn = n0 + wn + j * 8 + 2 * (lane & 3);
                *reinterpret_cast<float2*>(base + (size_t)gm * N + gn) =
                    make_float2(acc[im][j][0], acc[im][j][1]);
                *reinterpret_cast<float2*>(base + (size_t)(gm + 8) * N + gn) =
                    make_float2(acc[im][j][2], acc[im][j][3]);
            }
        }
    } else if (mode == 1) {
        #pragma unroll
        for (int im = 0; im < 2; im++) {
            int gm = m0 + wm + im * 16 + (lane >> 2);
            #pragma unroll
            for (int j = 0; j < 8; j++) {
                int gn = n0 + wn + j * 8 + 2 * (lane & 3);
                float b0 = bias[gn], b1 = bias[gn + 1];
                uint32_t h, l;
                split2h(acc[im][j][0] + b0, acc[im][j][1] + b1, h, l);
                *reinterpret_cast<uint32_t*>(pCh + (size_t)gm * N + gn) = h;
                *reinterpret_cast<uint32_t*>(pCl + (size_t)gm * N + gn) = l;
                split2h(acc[im][j][2] + b0, acc[im][j][3] + b1, h, l);
                *reinterpret_cast<uint32_t*>(pCh + (size_t)(gm + 8) * N + gn) = h;
                *reinterpret_cast<uint32_t*>(pCl + (size_t)(gm + 8) * N + gn) = l;
            }
        }
    } else if (mode == 2) {
        float* sC = reinterpret_cast<float*>(smem);
        #pragma unroll
        for (int im = 0; im < 2; im++) {
            int rr = wm + im * 16 + (lane >> 2);
            #pragma unroll
            for (int j = 0; j < 8; j++) {
                int cc = wn + j * 8 + 2 * (lane & 3);
                sC[rr * 128 + cc]           = acc[im][j][0];
                sC[rr * 128 + cc + 1]       = acc[im][j][1];
                sC[(rr + 8) * 128 + cc]     = acc[im][j][2];
                sC[(rr + 8) * 128 + cc + 1] = acc[im][j][3];
            }
        }
        __syncthreads();
        const int nl = tid & 127;
        const int mh = tid >> 7;
        const float bv = bias ? bias[n0 + nl] : 0.f;
        const int b  = m0 >> 11;
        const int l0 = (m0 & (LL - 1)) + mh * 64;
        size_t base = ((size_t)b * DD + (n0 + nl)) * (size_t)LL + l0;
        for (int i = 0; i < 64; i += 8) {
            uint32_t w[4];
            #pragma unroll
            for (int p = 0; p < 4; p++) {
                float v0 = sC[(mh * 64 + i + 2 * p)     * 128 + nl] + bv;
                float v1 = sC[(mh * 64 + i + 2 * p + 1) * 128 + nl] + bv;
                w[p] = packh2(v0, v1);
            }
            *reinterpret_cast<uint4*>(Ch + base + i) =
                make_uint4(w[0], w[1], w[2], w[3]);
        }
    } else {
        // mode 3: E' = exp(S)*2^-26 fp16 pair + per-tile fp32 column sums
        float cs[8][2];
        #pragma unroll
        for (int j = 0; j < 8; j++) { cs[j][0] = 0.f; cs[j][1] = 0.f; }
        #pragma unroll
        for (int im = 0; im < 2; im++) {
            int gm = m0 + wm + im * 16 + (lane >> 2);
            #pragma unroll
            for (int j = 0; j < 8; j++) {
                int gn = n0 + wn + j * 8 + 2 * (lane & 3);
                float e0 = fast_exp_s26(acc[im][j][0]);
                float e1 = fast_exp_s26(acc[im][j][1]);
                float e2 = fast_exp_s26(acc[im][j][2]);
                float e3 = fast_exp_s26(acc[im][j][3]);
                uint32_t h, l;
                split2h(e0, e1, h, l);
                *reinterpret_cast<uint32_t*>(pCh + (size_t)gm * N + gn) = h;
                *reinterpret_cast<uint32_t*>(pCl + (size_t)gm * N + gn) = l;
                split2h(e2, e3, h, l);
                *reinterpret_cast<uint32_t*>(pCh + (size_t)(gm + 8) * N + gn) = h;
                *reinterpret_cast<uint32_t*>(pCl + (size_t)(gm + 8) * N + gn) = l;
                cs[j][0] += e0 + e2;
                cs[j][1] += e1 + e3;
            }
        }
        #pragma unroll
        for (int j = 0; j < 8; j++) {
            #pragma unroll
            for (int off = 4; off <= 16; off <<= 1) {
                cs[j][0] += __shfl_xor_sync(0xffffffffu, cs[j][0], off);
                cs[j][1] += __shfl_xor_sync(0xffffffffu, cs[j][1], off);
            }
        }
        float* sPart = reinterpret_cast<float*>(smem);
        if (lane < 4) {
            int mwarp = warp >> 1;
            #pragma unroll
            for (int j = 0; j < 8; j++) {
                int col = wn + j * 8 + 2 * (lane & 3);
                sPart[mwarp * 128 + col]     = cs[j][0];
                sPart[mwarp * 128 + col + 1] = cs[j][1];
            }
        }
        __syncthreads();
        if (tid < 128) {
            float tot = sPart[tid] + sPart[128 + tid] +
                        sPart[256 + tid] + sPart[384 + tid];
            g_pz[(size_t)blockIdx.y * BL + bz * LL + n0 + tid] = tot;
        }
    }
}

// ---------------------------------------------------------------------------
// fused fp32 -> fp16 hi/lo split for 3 arrays
// ---------------------------------------------------------------------------
__global__ void __launch_bounds__(256) cvt3(
    const float* __restrict__ s0, const float* __restrict__ s1,
    const float* __restrict__ s2,
    __half* __restrict__ h0, __half* __restrict__ l0,
    __half* __restrict__ h1, __half* __restrict__ l1,
    __half* __restrict__ h2, __half* __restrict__ l2)
{
    const float* s = (blockIdx.y == 0) ? s0 : (blockIdx.y == 1) ? s1 : s2;
    __half* h = (blockIdx.y == 0) ? h0 : (blockIdx.y == 1) ? h1 : h2;
    __half* l = (blockIdx.y == 0) ? l0 : (blockIdx.y == 1) ? l1 : l2;
    size_t i = (size_t)blockIdx.x * 256 + threadIdx.x;
    float4 v = reinterpret_cast<const float4*>(s)[i];
    uint32_t ha, la, hb, lb;
    split2h(v.x, v.y, ha, la);
    split2h(v.z, v.w, hb, lb);
    reinterpret_cast<uint32_t*>(h)[2 * i + 0] = ha;
    reinterpret_cast<uint32_t*>(h)[2 * i + 1] = hb;
    reinterpret_cast<uint32_t*>(l)[2 * i + 0] = la;
    reinterpret_cast<uint32_t*>(l)[2 * i + 1] = lb;
}

__global__ void __launch_bounds__(256) colsum_combine()
{
    const int c = blockIdx.x * 256 + threadIdx.x;
    float z = 0.f;
    #pragma unroll
    for (int s = 0; s < 16; s++) z += g_pz[(size_t)s * BL + c];
    g_crcpz[c] = 1.f / z;
}

// vpT[b][d][l] *= rz[b][l], single fp16 plane
__global__ void __launch_bounds__(256) scale_vpT()
{
    size_t idx = (size_t)blockIdx.x * 256 + threadIdx.x;
    size_t e0  = idx * 8;
    int l   = (int)(e0 & (LL - 1));
    int row = (int)(e0 >> 11);
    int b   = row >> 9;
    uint4 hv = reinterpret_cast<uint4*>(g_vpTh)[idx];
    const float* rz = &g_crcpz[b * LL + l];
    uint32_t hw[4] = {hv.x, hv.y, hv.z, hv.w};
    #pragma unroll
    for (int p = 0; p < 4; p++) {
        __half2 hh;
        memcpy(&hh, &hw[p], 4);
        float v0 = __half2float(hh.x) * rz[2 * p];
        float v1 = __half2float(hh.y) * rz[2 * p + 1];
        hw[p] = packh2(v0, v1);
    }
    reinterpret_cast<uint4*>(g_vpTh)[idx] = make_uint4(hw[0], hw[1], hw[2], hw[3]);
}

// ---------------------------------------------------------------------------
extern "C" void kernel_launch(void* const* d_in, const int* in_sizes, int n_in,
                              void* d_out, int out_size)
{
    const float* q  = (const float*)d_in[0];
    const float* k  = (const float*)d_in[1];
    const float* v  = (const float*)d_in[2];
    const float* Wq = (const float*)d_in[3];
    const float* bq = (const float*)d_in[4];
    const float* Wk = (const float*)d_in[5];
    const float* bk = (const float*)d_in[6];
    const float* Wv = (const float*)d_in[7];
    const float* bv = (const float*)d_in[8];
    float* out = (float*)d_out;

    __half *qh, *ql, *kh, *kl, *vh, *vl;
    __half *Wqh, *Wql, *Wkh, *Wkl, *Wvh, *Wvl;
    __half *qph, *qpl, *kph, *kpl, *vpTh, *Eh, *El;
    cudaGetSymbolAddress((void**)&qh, g_qh);   cudaGetSymbolAddress((void**)&ql, g_ql);
    cudaGetSymbolAddress((void**)&kh, g_kh);   cudaGetSymbolAddress((void**)&kl, g_kl);
    cudaGetSymbolAddress((void**)&vh, g_vh);   cudaGetSymbolAddress((void**)&vl, g_vl);
    cudaGetSymbolAddress((void**)&Wqh, g_Wqh); cudaGetSymbolAddress((void**)&Wql, g_Wql);
    cudaGetSymbolAddress((void**)&Wkh, g_Wkh); cudaGetSymbolAddress((void**)&Wkl, g_Wkl);
    cudaGetSymbolAddress((void**)&Wvh, g_Wvh); cudaGetSymbolAddress((void**)&Wvl, g_Wvl);
    cudaGetSymbolAddress((void**)&qph, g_qph); cudaGetSymbolAddress((void**)&qpl, g_qpl);
    cudaGetSymbolAddress((void**)&kph, g_kph); cudaGetSymbolAddress((void**)&kpl, g_kpl);
    cudaGetSymbolAddress((void**)&vpTh, g_vpTh);
    cudaGetSymbolAddress((void**)&Eh, g_Eh);   cudaGetSymbolAddress((void**)&El, g_El);

    cudaFuncSetAttribute(gemm_mma<3>, cudaFuncAttributeMaxDynamicSharedMemorySize,
                         SMEM_BYTES);
    cudaFuncSetAttribute(gemm_mma<2>, cudaFuncAttributeMaxDynamicSharedMemorySize,
                         SMEM_BYTES);

    // 1) splits
    {
        dim3 gi((BL * DD) / 1024, 3);
        cvt3<<<gi, 256>>>(q, k, v, qh, ql, kh, kl, vh, vl);
        dim3 gw((DD * DD) / 1024, 3);
        cvt3<<<gw, 256>>>(Wq, Wk, Wv, Wqh, Wql, Wkh, Wkl, Wvh, Wvl);
    }

    // 2) projections (fp16 3-term)
    {
        dim3 gp(DD / 128, BL / 128, 1);
        gemm_mma<3><<<gp, 256, SMEM_BYTES>>>(qh, ql, Wqh, Wql, bq,
                                             nullptr, qph, qpl, DD, DD, 0, 0, 0, 1);
        gemm_mma<3><<<gp, 256, SMEM_BYTES>>>(kh, kl, Wkh, Wkl, bk,
                                             nullptr, kph, kpl, DD, DD, 0, 0, 0, 1);
        gemm_mma<3><<<gp, 256, SMEM_BYTES>>>(vh, vl, Wvh, Wvl, bv,
                                             nullptr, vpTh, nullptr, DD, DD, 0, 0, 0, 2);
    }

    // 3) E'[b] = exp(qp kp^T)*2^-26 fp16 pair + colsums
    {
        dim3 gs(LL / 128, LL / 128, BB);
        gemm_mma<3><<<gs, 256, SMEM_BYTES>>>(qph, qpl, kph, kpl, nullptr,
                                             nullptr, Eh, El,
                                             LL, DD,
                                             (size_t)LL * DD, (size_t)LL * DD,
                                             (size_t)LL * LL, 3);
    }

    // 4) rz = 1/colsum(E'); fold into vpT (single plane)
    colsum_combine<<<BL / 256, 256>>>();
    scale_vpT<<<(BL * DD) / (8 * 256), 256>>>();

    // 5) out[b] = E'[b] @ vpT'[b]^T  (2-term: (Eh+El) * vh)
    {
        dim3 go(DD / 128, LL / 128, BB);
        gemm_mma<2><<<go, 256, SMEM_BYTES>>>(Eh, El, vpTh, nullptr, nullptr,
                                             out, nullptr, nullptr,
                                             DD, LL,
                                             (size_t)LL * LL, (size_t)DD * LL,
                                             (size_t)LL * DD, 0);
    }
}

// round 9
// speedup vs baseline: 1.3711x; 1.1515x over previous
#include <cuda_runtime.h>
#include <cuda_fp16.h>
#include <cstdint>
#include <math.h>

#define BB 8
#define LL 2048
#define DD 512
#define BL (BB*LL)

// ---------------------------------------------------------------------------
// Device scratch
// ---------------------------------------------------------------------------
__device__ __align__(256) __half g_Eh[(size_t)BB*LL*LL];  // E' = exp(S)*2^-26, fp16
__device__ __align__(256) __half g_qh[BL*DD], g_ql[BL*DD];
__device__ __align__(256) __half g_kh[BL*DD], g_kl[BL*DD];
__device__ __align__(256) __half g_vh[BL*DD], g_vl[BL*DD];
__device__ __align__(256) __half g_Wqh[DD*DD], g_Wql[DD*DD];
__device__ __align__(256) __half g_Wkh[DD*DD], g_Wkl[DD*DD];
__device__ __align__(256) __half g_Wvh[DD*DD], g_Wvl[DD*DD];
__device__ __align__(256) __half g_qph[BL*DD], g_qpl[BL*DD];
__device__ __align__(256) __half g_kph[BL*DD], g_kpl[BL*DD];
__device__ __align__(256) __half g_vpTh[BL*DD];           // [B][D][L] single plane
__device__ __align__(256) float g_crcpz[BL];
__device__ __align__(256) float g_pz[16*BL];

// ---------------------------------------------------------------------------
// Portable PTX helpers (sm_80+)
// ---------------------------------------------------------------------------
__device__ __forceinline__ uint32_t smem_u32(const void* p) {
    uint32_t a;
    asm("{ .reg .u64 t; cvta.to.shared.u64 t, %1; cvt.u32.u64 %0, t; }"
        : "=r"(a) : "l"(p));
    return a;
}

#define CP16(dst, src) \
    asm volatile("cp.async.cg.shared.global [%0], [%1], 16;" \
                 :: "r"(dst), "l"(src) : "memory")
#define CP_COMMIT() asm volatile("cp.async.commit_group;" ::: "memory")
#define CP_WAIT1()  asm volatile("cp.async.wait_group 1;" ::: "memory")

#define LDSM4(r0, r1, r2, r3, addr) \
    asm volatile("ldmatrix.sync.aligned.m8n8.x4.shared.b16 {%0,%1,%2,%3}, [%4];" \
                 : "=r"(r0), "=r"(r1), "=r"(r2), "=r"(r3) : "r"(addr))

#define MMAH(d, a, b) \
    asm volatile("mma.sync.aligned.m16n8k16.row.col.f32.f16.f16.f32 " \
                 "{%0,%1,%2,%3}, {%4,%5,%6,%7}, {%8,%9}, {%0,%1,%2,%3};" \
                 : "+f"((d)[0]), "+f"((d)[1]), "+f"((d)[2]), "+f"((d)[3]) \
                 : "r"((a)[0]), "r"((a)[1]), "r"((a)[2]), "r"((a)[3]), \
                   "r"((b)[0]), "r"((b)[1]))

__device__ __forceinline__ uint32_t packh2(float a, float b) {
    __half2 t = __floats2half2_rn(a, b);
    uint32_t u; memcpy(&u, &t, 4); return u;
}
__device__ __forceinline__ void split2h(float v0, float v1,
                                        uint32_t& h, uint32_t& l) {
    float h0 = __half2float(__float2half_rn(v0));
    float h1 = __half2float(__float2half_rn(v1));
    h = packh2(v0, v1);
    l = packh2(v0 - h0, v1 - h1);
}

// Fast exp * 2^-26 on the FMA pipe (rel err ~2e-6), clamped for fp16 storage
__device__ __forceinline__ float fast_exp_s26(float x) {
    float y = x * 1.4426950408889634f;
    float t = y + 12582912.f;
    int   n = __float_as_int(t) - 0x4B400000;
    t -= 12582912.f;
    float f = y - t;
    float p = 1.3333558146e-3f;
    p = fmaf(p, f, 9.6181291076e-3f);
    p = fmaf(p, f, 5.5504108664e-2f);
    p = fmaf(p, f, 2.4022650696e-1f);
    p = fmaf(p, f, 6.9314718056e-1f);
    p = fmaf(p, f, 1.0f);
    float e = __int_as_float(__float_as_int(p) + ((n - 26) << 23));
    return fminf(e, 60000.f);
}

// smem: 3 stages x 4 planes x 8KB = 96KB
#define PL_AH 0
#define PL_AL 8192
#define PL_BH 16384
#define PL_BL 24576
#define STAGE_BYTES 32768
#define SMEM_BYTES 98304

__device__ __forceinline__ uint32_t swz(int r, int kc) {
    return (uint32_t)(r * 64 + ((kc ^ ((r >> 1) & 3)) << 4));
}

// ---------------------------------------------------------------------------
// NT GEMM, fp16 split precision, mma.sync.m16n8k16, 3-stage cp.async ring.
// TERMS=3: Ah*Bh + Ah*Bl + Al*Bh.  TERMS=1: Ah*Bh only.
// mode 0: Cf fp32 row-major.
// mode 1: Ch/Cl fp16 planes row-major (+bias).
// mode 2: Ch fp16 SINGLE plane transposed -> [b][n][m%LL] (+bias).
// mode 3: Ch = exp(C)*2^-26 fp16 SINGLE plane (coalesced via smem) + colsums.
// ---------------------------------------------------------------------------
template<int TERMS>
__global__ void __launch_bounds__(256, 2) gemm_mma(
    const __half* __restrict__ Ah, const __half* __restrict__ Al,
    const __half* __restrict__ Bh, const __half* __restrict__ Bl,
    const float* __restrict__ bias,
    float* __restrict__ Cf,
    __half* __restrict__ Ch, __half* __restrict__ Cl,
    int N, int K,
    size_t sAz, size_t sBz, size_t sCz,
    int mode)
{
    extern __shared__ char smem[];
    const uint32_t sbase = smem_u32(smem);
    const int tid  = threadIdx.x;
    const int lane = tid & 31;
    const int warp = tid >> 5;
    const int wm = (warp >> 1) * 32;
    const int wn = (warp & 1) * 64;
    const int m0 = blockIdx.y * 128, n0 = blockIdx.x * 128, bz = blockIdx.z;

    uint32_t dOff[2];
    size_t   gOff[2];
    #pragma unroll
    for (int i = 0; i < 2; i++) {
        int idx = tid + i * 256;
        int r = idx >> 2, c = idx & 3;
        dOff[i] = swz(r, c);
        gOff[i] = (size_t)r * K + c * 8;
    }
    uint32_t offA[2][2], offB[2][4];
    #pragma unroll
    for (int ks = 0; ks < 2; ks++) {
        int kc = ks * 2 + (lane >> 4);
        int rbase = (lane & 7) + ((lane >> 3) & 1) * 8;
        #pragma unroll
        for (int im = 0; im < 2; im++)
            offA[ks][im] = swz(wm + im * 16 + rbase, kc);
        #pragma unroll
        for (int j4 = 0; j4 < 4; j4++)
            offB[ks][j4] = swz(wn + j4 * 16 + rbase, kc);
    }

    const __half* pAh = Ah + bz * sAz + (size_t)m0 * K;
    const __half* pAl = (TERMS == 3) ? Al + bz * sAz + (size_t)m0 * K : nullptr;
    const __half* pBh = Bh + bz * sBz + (size_t)n0 * K;
    const __half* pBl = (TERMS == 3) ? Bl + bz * sBz + (size_t)n0 * K : nullptr;

    float acc[2][8][4];
    #pragma unroll
    for (int i = 0; i < 2; i++)
        #pragma unroll
        for (int j = 0; j < 8; j++)
            #pragma unroll
            for (int c = 0; c < 4; c++) acc[i][j][c] = 0.f;

#define LOAD_STAGE(slot, kt) do { \
    uint32_t so_ = sbase + (uint32_t)(slot) * STAGE_BYTES; \
    size_t ko_ = (size_t)(kt) * 32; \
    _Pragma("unroll") \
    for (int i_ = 0; i_ < 2; i_++) { \
        uint32_t d_ = so_ + dOff[i_]; \
        size_t g_ = gOff[i_] + ko_; \
        CP16(d_ + PL_AH, pAh + g_); \
        CP16(d_ + PL_BH, pBh + g_); \
        if (TERMS == 3) { \
            CP16(d_ + PL_AL, pAl + g_); \
            CP16(d_ + PL_BL, pBl + g_); \
        } \
    } \
} while (0)

    const int nk = K >> 5;
    LOAD_STAGE(0, 0); CP_COMMIT();
    LOAD_STAGE(1, 1); CP_COMMIT();

    int slot = 0, nslot = 2;
    for (int kt = 0; kt < nk; kt++) {
        CP_WAIT1();
        __syncthreads();
        if (kt + 2 < nk) LOAD_STAGE(nslot, kt + 2);
        CP_COMMIT();

        const uint32_t so = sbase + (uint32_t)slot * STAGE_BYTES;
        #pragma unroll
        for (int ks = 0; ks < 2; ks++) {
            uint32_t a_h[2][4], a_l[2][4];
            #pragma unroll
            for (int im = 0; im < 2; im++) {
                uint32_t ad = so + offA[ks][im];
                LDSM4(a_h[im][0], a_h[im][1], a_h[im][2], a_h[im][3], ad + PL_AH);
                if (TERMS == 3)
                    LDSM4(a_l[im][0], a_l[im][1], a_l[im][2], a_l[im][3], ad + PL_AL);
            }
            uint32_t b_h[8][2], b_l[8][2];
            #pragma unroll
            for (int j4 = 0; j4 < 4; j4++) {
                uint32_t bd = so + offB[ks][j4];
                LDSM4(b_h[2*j4][0], b_h[2*j4+1][0], b_h[2*j4][1], b_h[2*j4+1][1],
                      bd + PL_BH);
                if (TERMS == 3)
                    LDSM4(b_l[2*j4][0], b_l[2*j4+1][0], b_l[2*j4][1], b_l[2*j4+1][1],
                          bd + PL_BL);
            }
            #pragma unroll
            for (int im = 0; im < 2; im++)
                #pragma unroll
                for (int j = 0; j < 8; j++) MMAH(acc[im][j], a_h[im], b_h[j]);
            if (TERMS == 3) {
                #pragma unroll
                for (int im = 0; im < 2; im++)
                    #pragma unroll
                    for (int j = 0; j < 8; j++) MMAH(acc[im][j], a_h[im], b_l[j]);
                #pragma unroll
                for (int im = 0; im < 2; im++)
                    #pragma unroll
                    for (int j = 0; j < 8; j++) MMAH(acc[im][j], a_l[im], b_h[j]);
            }
        }
        slot = (slot == 2) ? 0 : slot + 1;
        nslot = (nslot == 2) ? 0 : nslot + 1;
    }
#undef LOAD_STAGE
    __syncthreads();

    __half* pCh = Ch + bz * sCz;
    __half* pCl = Cl ? Cl + bz * sCz : nullptr;

    if (mode == 0) {
        float* base = Cf + bz * sCz;
        #pragma unroll
        for (int im = 0; im < 2; im++) {
            int gm = m0 + wm + im * 16 + (lane >> 2);
            #pragma unroll
            for (int j = 0; j < 8; j++) {
                int gn = n0 + wn + j * 8 + 2 * (lane & 3);
                *reinterpret_cast<float2*>(base + (size_t)gm * N + gn) =
                    make_float2(acc[im][j][0], acc[im][j][1]);
                *reinterpret_cast<float2*>(base + (size_t)(gm + 8) * N + gn) =
                    make_float2(acc[im][j][2], acc[im][j][3]);
            }
        }
    } else if (mode == 1) {
        #pragma unroll
        for (int im = 0; im < 2; im++) {
            int gm = m0 + wm + im * 16 + (lane >> 2);
            #pragma unroll
            for (int j = 0; j < 8; j++) {
                int gn = n0 + wn + j * 8 + 2 * (lane & 3);
                float b0 = bias[gn], b1 = bias[gn + 1];
                uint32_t h, l;
                split2h(acc[im][j][0] + b0, acc[im][j][1] + b1, h, l);
                *reinterpret_cast<uint32_t*>(pCh + (size_t)gm * N + gn) = h;
                *reinterpret_cast<uint32_t*>(pCl + (size_t)gm * N + gn) = l;
                split2h(acc[im][j][2] + b0, acc[im][j][3] + b1, h, l);
                *reinterpret_cast<uint32_t*>(pCh + (size_t)(gm + 8) * N + gn) = h;
                *reinterpret_cast<uint32_t*>(pCl + (size_t)(gm + 8) * N + gn) = l;
            }
        }
    } else if (mode == 2) {
        float* sC = reinterpret_cast<float*>(smem);
        #pragma unroll
        for (int im = 0; im < 2; im++) {
            int rr = wm + im * 16 + (lane >> 2);
            #pragma unroll
            for (int j = 0; j < 8; j++) {
                int cc = wn + j * 8 + 2 * (lane & 3);
                sC[rr * 128 + cc]           = acc[im][j][0];
                sC[rr * 128 + cc + 1]       = acc[im][j][1];
                sC[(rr + 8) * 128 + cc]     = acc[im][j][2];
                sC[(rr + 8) * 128 + cc + 1] = acc[im][j][3];
            }
        }
        __syncthreads();
        const int nl = tid & 127;
        const int mh = tid >> 7;
        const float bv = bias ? bias[n0 + nl] : 0.f;
        const int b  = m0 >> 11;
        const int l0 = (m0 & (LL - 1)) + mh * 64;
        size_t base = ((size_t)b * DD + (n0 + nl)) * (size_t)LL + l0;
        for (int i = 0; i < 64; i += 8) {
            uint32_t w[4];
            #pragma unroll
            for (int p = 0; p < 4; p++) {
                float v0 = sC[(mh * 64 + i + 2 * p)     * 128 + nl] + bv;
                float v1 = sC[(mh * 64 + i + 2 * p + 1) * 128 + nl] + bv;
                w[p] = packh2(v0, v1);
            }
            *reinterpret_cast<uint4*>(Ch + base + i) =
                make_uint4(w[0], w[1], w[2], w[3]);
        }
    } else {
        // mode 3: E' = exp(S)*2^-26 fp16 single plane, staged via smem for
        // fully coalesced stores; fp32 per-tile column sums.
        const int STR = 136;                     // padded smem stride (halves)
        __half* sE = reinterpret_cast<__half*>(smem);
        float* sPart = reinterpret_cast<float*>(smem + 128 * STR * 2 + 64);
        float cs[8][2];
        #pragma unroll
        for (int j = 0; j < 8; j++) { cs[j][0] = 0.f; cs[j][1] = 0.f; }
        #pragma unroll
        for (int im = 0; im < 2; im++) {
            int r0 = wm + im * 16 + (lane >> 2);
            #pragma unroll
            for (int j = 0; j < 8; j++) {
                int c0 = wn + j * 8 + 2 * (lane & 3);
                float e0 = fast_exp_s26(acc[im][j][0]);
                float e1 = fast_exp_s26(acc[im][j][1]);
                float e2 = fast_exp_s26(acc[im][j][2]);
                float e3 = fast_exp_s26(acc[im][j][3]);
                *reinterpret_cast<uint32_t*>(sE + r0 * STR + c0)       = packh2(e0, e1);
                *reinterpret_cast<uint32_t*>(sE + (r0 + 8) * STR + c0) = packh2(e2, e3);
                cs[j][0] += e0 + e2;
                cs[j][1] += e1 + e3;
            }
        }
        #pragma unroll
        for (int j = 0; j < 8; j++) {
            #pragma unroll
            for (int off = 4; off <= 16; off <<= 1) {
                cs[j][0] += __shfl_xor_sync(0xffffffffu, cs[j][0], off);
                cs[j][1] += __shfl_xor_sync(0xffffffffu, cs[j][1], off);
            }
        }
        __syncthreads();
        // coalesced copy out: thread -> (row, 64-col half-segment)
        {
            int row = tid >> 1;
            int seg = (tid & 1) * 64;
            size_t gb = (size_t)(m0 + row) * N + n0 + seg;
            #pragma unroll
            for (int i = 0; i < 8; i++) {
                uint4 w = *reinterpret_cast<uint4*>(sE + row * STR + seg + i * 8);
                *reinterpret_cast<uint4*>(pCh + gb + i * 8) = w;
            }
        }
        if (lane < 4) {
            int mwarp = warp >> 1;
            #pragma unroll
            for (int j = 0; j < 8; j++) {
                int col = wn + j * 8 + 2 * (lane & 3);
                sPart[mwarp * 128 + col]     = cs[j][0];
                sPart[mwarp * 128 + col + 1] = cs[j][1];
            }
        }
        __syncthreads();
        if (tid < 128) {
            float tot = sPart[tid] + sPart[128 + tid] +
                        sPart[256 + tid] + sPart[384 + tid];
            g_pz[(size_t)blockIdx.y * BL + bz * LL + n0 + tid] = tot;
        }
    }
}

// ---------------------------------------------------------------------------
// fused fp32 -> fp16 hi/lo split for 3 arrays
// ---------------------------------------------------------------------------
__global__ void __launch_bounds__(256) cvt3(
    const float* __restrict__ s0, const float* __restrict__ s1,
    const float* __restrict__ s2,
    __half* __restrict__ h0, __half* __restrict__ l0,
    __half* __restrict__ h1, __half* __restrict__ l1,
    __half* __restrict__ h2, __half* __restrict__ l2)
{
    const float* s = (blockIdx.y == 0) ? s0 : (blockIdx.y == 1) ? s1 : s2;
    __half* h = (blockIdx.y == 0) ? h0 : (blockIdx.y == 1) ? h1 : h2;
    __half* l = (blockIdx.y == 0) ? l0 : (blockIdx.y == 1) ? l1 : l2;
    size_t i = (size_t)blockIdx.x * 256 + threadIdx.x;
    float4 v = reinterpret_cast<const float4*>(s)[i];
    uint32_t ha, la, hb, lb;
    split2h(v.x, v.y, ha, la);
    split2h(v.z, v.w, hb, lb);
    reinterpret_cast<uint32_t*>(h)[2 * i + 0] = ha;
    reinterpret_cast<uint32_t*>(h)[2 * i + 1] = hb;
    reinterpret_cast<uint32_t*>(l)[2 * i + 0] = la;
    reinterpret_cast<uint32_t*>(l)[2 * i + 1] = lb;
}

__global__ void __launch_bounds__(256) colsum_combine()
{
    const int c = blockIdx.x * 256 + threadIdx.x;
    float z = 0.f;
    #pragma unroll
    for (int s = 0; s < 16; s++) z += g_pz[(size_t)s * BL + c];
    g_crcpz[c] = 1.f / z;
}

// vpT[b][d][l] *= rz[b][l], single fp16 plane
__global__ void __launch_bounds__(256) scale_vpT()
{
    size_t idx = (size_t)blockIdx.x * 256 + threadIdx.x;
    size_t e0  = idx * 8;
    int l   = (int)(e0 & (LL - 1));
    int row = (int)(e0 >> 11);
    int b   = row >> 9;
    uint4 hv = reinterpret_cast<uint4*>(g_vpTh)[idx];
    const float* rz = &g_crcpz[b * LL + l];
    uint32_t hw[4] = {hv.x, hv.y, hv.z, hv.w};
    #pragma unroll
    for (int p = 0; p < 4; p++) {
        __half2 hh;
        memcpy(&hh, &hw[p], 4);
        float v0 = __half2float(hh.x) * rz[2 * p];
        float v1 = __half2float(hh.y) * rz[2 * p + 1];
        hw[p] = packh2(v0, v1);
    }
    reinterpret_cast<uint4*>(g_vpTh)[idx] = make_uint4(hw[0], hw[1], hw[2], hw[3]);
}

// ---------------------------------------------------------------------------
extern "C" void kernel_launch(void* const* d_in, const int* in_sizes, int n_in,
                              void* d_out, int out_size)
{
    const float* q  = (const float*)d_in[0];
    const float* k  = (const float*)d_in[1];
    const float* v  = (const float*)d_in[2];
    const float* Wq = (const float*)d_in[3];
    const float* bq = (const float*)d_in[4];
    const float* Wk = (const float*)d_in[5];
    const float* bk = (const float*)d_in[6];
    const float* Wv = (const float*)d_in[7];
    const float* bv = (const float*)d_in[8];
    float* out = (float*)d_out;

    __half *qh, *ql, *kh, *kl, *vh, *vl;
    __half *Wqh, *Wql, *Wkh, *Wkl, *Wvh, *Wvl;
    __half *qph, *qpl, *kph, *kpl, *vpTh, *Eh;
    cudaGetSymbolAddress((void**)&qh, g_qh);   cudaGetSymbolAddress((void**)&ql, g_ql);
    cudaGetSymbolAddress((void**)&kh, g_kh);   cudaGetSymbolAddress((void**)&kl, g_kl);
    cudaGetSymbolAddress((void**)&vh, g_vh);   cudaGetSymbolAddress((void**)&vl, g_vl);
    cudaGetSymbolAddress((void**)&Wqh, g_Wqh); cudaGetSymbolAddress((void**)&Wql, g_Wql);
    cudaGetSymbolAddress((void**)&Wkh, g_Wkh); cudaGetSymbolAddress((void**)&Wkl, g_Wkl);
    cudaGetSymbolAddress((void**)&Wvh, g_Wvh); cudaGetSymbolAddress((void**)&Wvl, g_Wvl);
    cudaGetSymbolAddress((void**)&qph, g_qph); cudaGetSymbolAddress((void**)&qpl, g_qpl);
    cudaGetSymbolAddress((void**)&kph, g_kph); cudaGetSymbolAddress((void**)&kpl, g_kpl);
    cudaGetSymbolAddress((void**)&vpTh, g_vpTh);
    cudaGetSymbolAddress((void**)&Eh, g_Eh);

    cudaFuncSetAttribute(gemm_mma<3>, cudaFuncAttributeMaxDynamicSharedMemorySize,
                         SMEM_BYTES);
    cudaFuncSetAttribute(gemm_mma<1>, cudaFuncAttributeMaxDynamicSharedMemorySize,
                         SMEM_BYTES);

    // 1) splits
    {
        dim3 gi((BL * DD) / 1024, 3);
        cvt3<<<gi, 256>>>(q, k, v, qh, ql, kh, kl, vh, vl);
        dim3 gw((DD * DD) / 1024, 3);
        cvt3<<<gw, 256>>>(Wq, Wk, Wv, Wqh, Wql, Wkh, Wkl, Wvh, Wvl);
    }

    // 2) projections (fp16 3-term)
    {
        dim3 gp(DD / 128, BL / 128, 1);
        gemm_mma<3><<<gp, 256, SMEM_BYTES>>>(qh, ql, Wqh, Wql, bq,
                                             nullptr, qph, qpl, DD, DD, 0, 0, 0, 1);
        gemm_mma<3><<<gp, 256, SMEM_BYTES>>>(kh, kl, Wkh, Wkl, bk,
                                             nullptr, kph, kpl, DD, DD, 0, 0, 0, 1);
        gemm_mma<3><<<gp, 256, SMEM_BYTES>>>(vh, vl, Wvh, Wvl, bv,
                                             nullptr, vpTh, nullptr, DD, DD, 0, 0, 0, 2);
    }

    // 3) E'[b] = exp(qp kp^T)*2^-26, fp16 single plane + colsums
    {
        dim3 gs(LL / 128, LL / 128, BB);
        gemm_mma<3><<<gs, 256, SMEM_BYTES>>>(qph, qpl, kph, kpl, nullptr,
                                             nullptr, Eh, nullptr,
                                             LL, DD,
                                             (size_t)LL * DD, (size_t)LL * DD,
                                             (size_t)LL * LL, 3);
    }

    // 4) rz = 1/colsum(E'); fold into vpT
    colsum_combine<<<BL / 256, 256>>>();
    scale_vpT<<<(BL * DD) / (8 * 256), 256>>>();

    // 5) out[b] = E'[b] @ vpT'[b]^T  (1-term plain fp16 GEMM)
    {
        dim3 go(DD / 128, LL / 128, BB);
        gemm_mma<1><<<go, 256, SMEM_BYTES>>>(Eh, nullptr, vpTh, nullptr, nullptr,
                                             out, nullptr, nullptr,
                                             DD, LL,
                                             (size_t)LL * LL, (size_t)DD * LL,
                                             (size_t)LL * DD, 0);
    }
}

// round 10
// speedup vs baseline: 1.5180x; 1.1071x over previous
#include <cuda_runtime.h>
#include <cuda_fp16.h>
#include <cstdint>
#include <math.h>

#define BB 8
#define LL 2048
#define DD 512
#define BL (BB*LL)

// ---------------------------------------------------------------------------
// Device scratch
// ---------------------------------------------------------------------------
__device__ __align__(256) __half g_Eh[(size_t)BB*LL*LL];  // E' = exp(S)*2^-26, fp16
__device__ __align__(256) __half g_qh[BL*DD], g_ql[BL*DD];
__device__ __align__(256) __half g_kh[BL*DD], g_kl[BL*DD];
__device__ __align__(256) __half g_vh[BL*DD], g_vl[BL*DD];
__device__ __align__(256) __half g_Wqh[DD*DD], g_Wql[DD*DD];
__device__ __align__(256) __half g_Wkh[DD*DD], g_Wkl[DD*DD];
__device__ __align__(256) __half g_Wvh[DD*DD], g_Wvl[DD*DD];
__device__ __align__(256) __half g_qph[BL*DD], g_qpl[BL*DD];
__device__ __align__(256) __half g_kph[BL*DD], g_kpl[BL*DD];
__device__ __align__(256) __half g_vpTh[BL*DD];           // [B][D][L] single plane
__device__ __align__(256) float g_crcpz[BL];
__device__ __align__(256) float g_pz[16*BL];

// pointer set for z-fused projection launches
struct ProjArgs {
    const __half *Ah0, *Al0, *Bh0, *Bl0; const float* b0; __half *Ch0, *Cl0;
    const __half *Ah1, *Al1, *Bh1, *Bl1; const float* b1; __half *Ch1, *Cl1;
};

// ---------------------------------------------------------------------------
// Portable PTX helpers (sm_80+)
// ---------------------------------------------------------------------------
__device__ __forceinline__ uint32_t smem_u32(const void* p) {
    uint32_t a;
    asm("{ .reg .u64 t; cvta.to.shared.u64 t, %1; cvt.u32.u64 %0, t; }"
        : "=r"(a) : "l"(p));
    return a;
}

#define CP16(dst, src) \
    asm volatile("cp.async.cg.shared.global [%0], [%1], 16;" \
                 :: "r"(dst), "l"(src) : "memory")
#define CP_COMMIT() asm volatile("cp.async.commit_group;" ::: "memory")
#define CP_WAIT1()  asm volatile("cp.async.wait_group 1;" ::: "memory")

#define LDSM4(r0, r1, r2, r3, addr) \
    asm volatile("ldmatrix.sync.aligned.m8n8.x4.shared.b16 {%0,%1,%2,%3}, [%4];" \
                 : "=r"(r0), "=r"(r1), "=r"(r2), "=r"(r3) : "r"(addr))

#define MMAH(d, a, b) \
    asm volatile("mma.sync.aligned.m16n8k16.row.col.f32.f16.f16.f32 " \
                 "{%0,%1,%2,%3}, {%4,%5,%6,%7}, {%8,%9}, {%0,%1,%2,%3};" \
                 : "+f"((d)[0]), "+f"((d)[1]), "+f"((d)[2]), "+f"((d)[3]) \
                 : "r"((a)[0]), "r"((a)[1]), "r"((a)[2]), "r"((a)[3]), \
                   "r"((b)[0]), "r"((b)[1]))

__device__ __forceinline__ uint32_t packh2(float a, float b) {
    __half2 t = __floats2half2_rn(a, b);
    uint32_t u; memcpy(&u, &t, 4); return u;
}
__device__ __forceinline__ void split2h(float v0, float v1,
                                        uint32_t& h, uint32_t& l) {
    float h0 = __half2float(__float2half_rn(v0));
    float h1 = __half2float(__float2half_rn(v1));
    h = packh2(v0, v1);
    l = packh2(v0 - h0, v1 - h1);
}

// Fast exp * 2^-26 on the FMA pipe (rel err ~2e-6), clamped for fp16 storage
__device__ __forceinline__ float fast_exp_s26(float x) {
    float y = x * 1.4426950408889634f;
    float t = y + 12582912.f;
    int   n = __float_as_int(t) - 0x4B400000;
    t -= 12582912.f;
    float f = y - t;
    float p = 1.3333558146e-3f;
    p = fmaf(p, f, 9.6181291076e-3f);
    p = fmaf(p, f, 5.5504108664e-2f);
    p = fmaf(p, f, 2.4022650696e-1f);
    p = fmaf(p, f, 6.9314718056e-1f);
    p = fmaf(p, f, 1.0f);
    float e = __int_as_float(__float_as_int(p) + ((n - 26) << 23));
    return fminf(e, 60000.f);
}

// smem: 3 stages x 4 planes x 8KB = 96KB
#define PL_AH 0
#define PL_AL 8192
#define PL_BH 16384
#define PL_BL 24576
#define STAGE_BYTES 32768
#define SMEM_BYTES 98304

__device__ __forceinline__ uint32_t swz(int r, int kc) {
    return (uint32_t)(r * 64 + ((kc ^ ((r >> 1) & 3)) << 4));
}

// ---------------------------------------------------------------------------
// NT GEMM, fp16 split precision, mma.sync.m16n8k16, 3-stage cp.async ring.
// TERMS=3: Ah*Bh + Ah*Bl + Al*Bh.  TERMS=1: Ah*Bh only.
// ZSEL: pointer set chosen by blockIdx.z from ProjArgs (strides must be 0).
// mode 0: Cf fp32 row-major.
// mode 1: Ch/Cl fp16 planes row-major (+bias).
// mode 2: Ch fp16 SINGLE plane transposed -> [b][n][m%LL] (+bias).
// mode 3: Ch = exp(C)*2^-26 fp16 SINGLE plane (coalesced via smem) + colsums.
// ---------------------------------------------------------------------------
template<int TERMS, bool ZSEL>
__global__ void __launch_bounds__(256, 2) gemm_mma(
    const __half* __restrict__ Ah, const __half* __restrict__ Al,
    const __half* __restrict__ Bh, const __half* __restrict__ Bl,
    const float* __restrict__ bias,
    float* __restrict__ Cf,
    __half* __restrict__ Ch, __half* __restrict__ Cl,
    int N, int K,
    size_t sAz, size_t sBz, size_t sCz,
    int mode, ProjArgs pa)
{
    extern __shared__ char smem[];
    const uint32_t sbase = smem_u32(smem);
    const int tid  = threadIdx.x;
    const int lane = tid & 31;
    const int warp = tid >> 5;
    const int wm = (warp >> 1) * 32;
    const int wn = (warp & 1) * 64;
    const int m0 = blockIdx.y * 128, n0 = blockIdx.x * 128, bz = blockIdx.z;

    if (ZSEL) {
        if (bz == 1) {
            Ah = pa.Ah1; Al = pa.Al1; Bh = pa.Bh1; Bl = pa.Bl1;
            bias = pa.b1; Ch = pa.Ch1; Cl = pa.Cl1;
        } else {
            Ah = pa.Ah0; Al = pa.Al0; Bh = pa.Bh0; Bl = pa.Bl0;
            bias = pa.b0; Ch = pa.Ch0; Cl = pa.Cl0;
        }
        // strides are 0 for projections, so bz is inert below.
    }

    uint32_t dOff[2];
    size_t   gOff[2];
    #pragma unroll
    for (int i = 0; i < 2; i++) {
        int idx = tid + i * 256;
        int r = idx >> 2, c = idx & 3;
        dOff[i] = swz(r, c);
        gOff[i] = (size_t)r * K + c * 8;
    }
    uint32_t offA[2][2], offB[2][4];
    #pragma unroll
    for (int ks = 0; ks < 2; ks++) {
        int kc = ks * 2 + (lane >> 4);
        int rbase = (lane & 7) + ((lane >> 3) & 1) * 8;
        #pragma unroll
        for (int im = 0; im < 2; im++)
            offA[ks][im] = swz(wm + im * 16 + rbase, kc);
        #pragma unroll
        for (int j4 = 0; j4 < 4; j4++)
            offB[ks][j4] = swz(wn + j4 * 16 + rbase, kc);
    }

    const __half* pAh = Ah + bz * sAz + (size_t)m0 * K;
    const __half* pAl = (TERMS == 3) ? Al + bz * sAz + (size_t)m0 * K : nullptr;
    const __half* pBh = Bh + bz * sBz + (size_t)n0 * K;
    const __half* pBl = (TERMS == 3) ? Bl + bz * sBz + (size_t)n0 * K : nullptr;

    float acc[2][8][4];
    #pragma unroll
    for (int i = 0; i < 2; i++)
        #pragma unroll
        for (int j = 0; j < 8; j++)
            #pragma unroll
            for (int c = 0; c < 4; c++) acc[i][j][c] = 0.f;

#define LOAD_STAGE(slot, kt) do { \
    uint32_t so_ = sbase + (uint32_t)(slot) * STAGE_BYTES; \
    size_t ko_ = (size_t)(kt) * 32; \
    _Pragma("unroll") \
    for (int i_ = 0; i_ < 2; i_++) { \
        uint32_t d_ = so_ + dOff[i_]; \
        size_t g_ = gOff[i_] + ko_; \
        CP16(d_ + PL_AH, pAh + g_); \
        CP16(d_ + PL_BH, pBh + g_); \
        if (TERMS == 3) { \
            CP16(d_ + PL_AL, pAl + g_); \
            CP16(d_ + PL_BL, pBl + g_); \
        } \
    } \
} while (0)

    const int nk = K >> 5;
    LOAD_STAGE(0, 0); CP_COMMIT();
    LOAD_STAGE(1, 1); CP_COMMIT();

    int slot = 0, nslot = 2;
    for (int kt = 0; kt < nk; kt++) {
        CP_WAIT1();
        __syncthreads();
        if (kt + 2 < nk) LOAD_STAGE(nslot, kt + 2);
        CP_COMMIT();

        const uint32_t so = sbase + (uint32_t)slot * STAGE_BYTES;
        #pragma unroll
        for (int ks = 0; ks < 2; ks++) {
            uint32_t a_h[2][4], a_l[2][4];
            #pragma unroll
            for (int im = 0; im < 2; im++) {
                uint32_t ad = so + offA[ks][im];
                LDSM4(a_h[im][0], a_h[im][1], a_h[im][2], a_h[im][3], ad + PL_AH);
                if (TERMS == 3)
                    LDSM4(a_l[im][0], a_l[im][1], a_l[im][2], a_l[im][3], ad + PL_AL);
            }
            uint32_t b_h[8][2], b_l[8][2];
            #pragma unroll
            for (int j4 = 0; j4 < 4; j4++) {
                uint32_t bd = so + offB[ks][j4];
                LDSM4(b_h[2*j4][0], b_h[2*j4+1][0], b_h[2*j4][1], b_h[2*j4+1][1],
                      bd + PL_BH);
                if (TERMS == 3)
                    LDSM4(b_l[2*j4][0], b_l[2*j4+1][0], b_l[2*j4][1], b_l[2*j4+1][1],
                          bd + PL_BL);
            }
            #pragma unroll
            for (int im = 0; im < 2; im++)
                #pragma unroll
                for (int j = 0; j < 8; j++) MMAH(acc[im][j], a_h[im], b_h[j]);
            if (TERMS == 3) {
                #pragma unroll
                for (int im = 0; im < 2; im++)
                    #pragma unroll
                    for (int j = 0; j < 8; j++) MMAH(acc[im][j], a_h[im], b_l[j]);
                #pragma unroll
                for (int im = 0; im < 2; im++)
                    #pragma unroll
                    for (int j = 0; j < 8; j++) MMAH(acc[im][j], a_l[im], b_h[j]);
            }
        }
        slot = (slot == 2) ? 0 : slot + 1;
        nslot = (nslot == 2) ? 0 : nslot + 1;
    }
#undef LOAD_STAGE
    __syncthreads();

    __half* pCh = Ch + bz * sCz;
    __half* pCl = Cl ? Cl + bz * sCz : nullptr;

    if (mode == 0) {
        float* base = Cf + bz * sCz;
        #pragma unroll
        for (int im = 0; im < 2; im++) {
            int gm = m0 + wm + im * 16 + (lane >> 2);
            #pragma unroll
            for (int j = 0; j < 8; j++) {
                int gn = n0 + wn + j * 8 + 2 * (lane & 3);
                *reinterpret_cast<float2*>(base + (size_t)gm * N + gn) =
                    make_float2(acc[im][j][0], acc[im][j][1]);
                *reinterpret_cast<float2*>(base + (size_t)(gm + 8) * N + gn) =
                    make_float2(acc[im][j][2], acc[im][j][3]);
            }
        }
    } else if (mode == 1) {
        #pragma unroll
        for (int im = 0; im < 2; im++) {
            int gm = m0 + wm + im * 16 + (lane >> 2);
            #pragma unroll
            for (int j = 0; j < 8; j++) {
                int gn = n0 + wn + j * 8 + 2 * (lane & 3);
                float b0 = bias[gn], b1 = bias[gn + 1];
                uint32_t h, l;
                split2h(acc[im][j][0] + b0, acc[im][j][1] + b1, h, l);
                *reinterpret_cast<uint32_t*>(pCh + (size_t)gm * N + gn) = h;
                *reinterpret_cast<uint32_t*>(pCl + (size_t)gm * N + gn) = l;
                split2h(acc[im][j][2] + b0, acc[im][j][3] + b1, h, l);
                *reinterpret_cast<uint32_t*>(pCh + (size_t)(gm + 8) * N + gn) = h;
                *reinterpret_cast<uint32_t*>(pCl + (size_t)(gm + 8) * N + gn) = l;
            }
        }
    } else if (mode == 2) {
        float* sC = reinterpret_cast<float*>(smem);
        #pragma unroll
        for (int im = 0; im < 2; im++) {
            int rr = wm + im * 16 + (lane >> 2);
            #pragma unroll
            for (int j = 0; j < 8; j++) {
                int cc = wn + j * 8 + 2 * (lane & 3);
                sC[rr * 128 + cc]           = acc[im][j][0];
                sC[rr * 128 + cc + 1]       = acc[im][j][1];
                sC[(rr + 8) * 128 + cc]     = acc[im][j][2];
                sC[(rr + 8) * 128 + cc + 1] = acc[im][j][3];
            }
        }
        __syncthreads();
        const int nl = tid & 127;
        const int mh = tid >> 7;
        const float bv = bias ? bias[n0 + nl] : 0.f;
        const int b  = m0 >> 11;
        const int l0 = (m0 & (LL - 1)) + mh * 64;
        size_t base = ((size_t)b * DD + (n0 + nl)) * (size_t)LL + l0;
        for (int i = 0; i < 64; i += 8) {
            uint32_t w[4];
            #pragma unroll
            for (int p = 0; p < 4; p++) {
                float v0 = sC[(mh * 64 + i + 2 * p)     * 128 + nl] + bv;
                float v1 = sC[(mh * 64 + i + 2 * p + 1) * 128 + nl] + bv;
                w[p] = packh2(v0, v1);
            }
            *reinterpret_cast<uint4*>(Ch + base + i) =
                make_uint4(w[0], w[1], w[2], w[3]);
        }
    } else {
        // mode 3: E' = exp(S)*2^-26 fp16 single plane via smem; fp32 colsums
        const int STR = 136;
        __half* sE = reinterpret_cast<__half*>(smem);
        float* sPart = reinterpret_cast<float*>(smem + 128 * STR * 2 + 64);
        float cs[8][2];
        #pragma unroll
        for (int j = 0; j < 8; j++) { cs[j][0] = 0.f; cs[j][1] = 0.f; }
        #pragma unroll
        for (int im = 0; im < 2; im++) {
            int r0 = wm + im * 16 + (lane >> 2);
            #pragma unroll
            for (int j = 0; j < 8; j++) {
                int c0 = wn + j * 8 + 2 * (lane & 3);
                float e0 = fast_exp_s26(acc[im][j][0]);
                float e1 = fast_exp_s26(acc[im][j][1]);
                float e2 = fast_exp_s26(acc[im][j][2]);
                float e3 = fast_exp_s26(acc[im][j][3]);
                *reinterpret_cast<uint32_t*>(sE + r0 * STR + c0)       = packh2(e0, e1);
                *reinterpret_cast<uint32_t*>(sE + (r0 + 8) * STR + c0) = packh2(e2, e3);
                cs[j][0] += e0 + e2;
                cs[j][1] += e1 + e3;
            }
        }
        #pragma unroll
        for (int j = 0; j < 8; j++) {
            #pragma unroll
            for (int off = 4; off <= 16; off <<= 1) {
                cs[j][0] += __shfl_xor_sync(0xffffffffu, cs[j][0], off);
                cs[j][1] += __shfl_xor_sync(0xffffffffu, cs[j][1], off);
            }
        }
        __syncthreads();
        {
            int row = tid >> 1;
            int seg = (tid & 1) * 64;
            size_t gb = (size_t)(m0 + row) * N + n0 + seg;
            #pragma unroll
            for (int i = 0; i < 8; i++) {
                uint4 w = *reinterpret_cast<uint4*>(sE + row * STR + seg + i * 8);
                *reinterpret_cast<uint4*>(pCh + gb + i * 8) = w;
            }
        }
        if (lane < 4) {
            int mwarp = warp >> 1;
            #pragma unroll
            for (int j = 0; j < 8; j++) {
                int col = wn + j * 8 + 2 * (lane & 3);
                sPart[mwarp * 128 + col]     = cs[j][0];
                sPart[mwarp * 128 + col + 1] = cs[j][1];
            }
        }
        __syncthreads();
        if (tid < 128) {
            float tot = sPart[tid] + sPart[128 + tid] +
                        sPart[256 + tid] + sPart[384 + tid];
            g_pz[(size_t)blockIdx.y * BL + bz * LL + n0 + tid] = tot;
        }
    }
}

// ---------------------------------------------------------------------------
// fused fp32 -> fp16 hi/lo split for 3 arrays
// ---------------------------------------------------------------------------
__global__ void __launch_bounds__(256) cvt3(
    const float* __restrict__ s0, const float* __restrict__ s1,
    const float* __restrict__ s2,
    __half* __restrict__ h0, __half* __restrict__ l0,
    __half* __restrict__ h1, __half* __restrict__ l1,
    __half* __restrict__ h2, __half* __restrict__ l2)
{
    const float* s = (blockIdx.y == 0) ? s0 : (blockIdx.y == 1) ? s1 : s2;
    __half* h = (blockIdx.y == 0) ? h0 : (blockIdx.y == 1) ? h1 : h2;
    __half* l = (blockIdx.y == 0) ? l0 : (blockIdx.y == 1) ? l1 : l2;
    size_t i = (size_t)blockIdx.x * 256 + threadIdx.x;
    float4 v = reinterpret_cast<const float4*>(s)[i];
    uint32_t ha, la, hb, lb;
    split2h(v.x, v.y, ha, la);
    split2h(v.z, v.w, hb, lb);
    reinterpret_cast<uint32_t*>(h)[2 * i + 0] = ha;
    reinterpret_cast<uint32_t*>(h)[2 * i + 1] = hb;
    reinterpret_cast<uint32_t*>(l)[2 * i + 0] = la;
    reinterpret_cast<uint32_t*>(l)[2 * i + 1] = lb;
}

__global__ void __launch_bounds__(256) colsum_combine()
{
    const int c = blockIdx.x * 256 + threadIdx.x;
    float z = 0.f;
    #pragma unroll
    for (int s = 0; s < 16; s++) z += g_pz[(size_t)s * BL + c];
    g_crcpz[c] = 1.f / z;
}

// vpT[b][d][l] *= rz[b][l], single fp16 plane
__global__ void __launch_bounds__(256) scale_vpT()
{
    size_t idx = (size_t)blockIdx.x * 256 + threadIdx.x;
    size_t e0  = idx * 8;
    int l   = (int)(e0 & (LL - 1));
    int row = (int)(e0 >> 11);
    int b   = row >> 9;
    uint4 hv = reinterpret_cast<uint4*>(g_vpTh)[idx];
    const float* rz = &g_crcpz[b * LL + l];
    uint32_t hw[4] = {hv.x, hv.y, hv.z, hv.w};
    #pragma unroll
    for (int p = 0; p < 4; p++) {
        __half2 hh;
        memcpy(&hh, &hw[p], 4);
        float v0 = __half2float(hh.x) * rz[2 * p];
        float v1 = __half2float(hh.y) * rz[2 * p + 1];
        hw[p] = packh2(v0, v1);
    }
    reinterpret_cast<uint4*>(g_vpTh)[idx] = make_uint4(hw[0], hw[1], hw[2], hw[3]);
}

// ---------------------------------------------------------------------------
extern "C" void kernel_launch(void* const* d_in, const int* in_sizes, int n_in,
                              void* d_out, int out_size)
{
    const float* q  = (const float*)d_in[0];
    const float* k  = (const float*)d_in[1];
    const float* v  = (const float*)d_in[2];
    const float* Wq = (const float*)d_in[3];
    const float* bq = (const float*)d_in[4];
    const float* Wk = (const float*)d_in[5];
    const float* bk = (const float*)d_in[6];
    const float* Wv = (const float*)d_in[7];
    const float* bv = (const float*)d_in[8];
    float* out = (float*)d_out;

    __half *qh, *ql, *kh, *kl, *vh, *vl;
    __half *Wqh, *Wql, *Wkh, *Wkl, *Wvh, *Wvl;
    __half *qph, *qpl, *kph, *kpl, *vpTh, *Eh;
    cudaGetSymbolAddress((void**)&qh, g_qh);   cudaGetSymbolAddress((void**)&ql, g_ql);
    cudaGetSymbolAddress((void**)&kh, g_kh);   cudaGetSymbolAddress((void**)&kl, g_kl);
    cudaGetSymbolAddress((void**)&vh, g_vh);   cudaGetSymbolAddress((void**)&vl, g_vl);
    cudaGetSymbolAddress((void**)&Wqh, g_Wqh); cudaGetSymbolAddress((void**)&Wql, g_Wql);
    cudaGetSymbolAddress((void**)&Wkh, g_Wkh); cudaGetSymbolAddress((void**)&Wkl, g_Wkl);
    cudaGetSymbolAddress((void**)&Wvh, g_Wvh); cudaGetSymbolAddress((void**)&Wvl, g_Wvl);
    cudaGetSymbolAddress((void**)&qph, g_qph); cudaGetSymbolAddress((void**)&qpl, g_qpl);
    cudaGetSymbolAddress((void**)&kph, g_kph); cudaGetSymbolAddress((void**)&kpl, g_kpl);
    cudaGetSymbolAddress((void**)&vpTh, g_vpTh);
    cudaGetSymbolAddress((void**)&Eh, g_Eh);

    cudaFuncSetAttribute((const void*)gemm_mma<3, false>,
                         cudaFuncAttributeMaxDynamicSharedMemorySize, SMEM_BYTES);
    cudaFuncSetAttribute((const void*)gemm_mma<3, true>,
                         cudaFuncAttributeMaxDynamicSharedMemorySize, SMEM_BYTES);
    cudaFuncSetAttribute((const void*)gemm_mma<1, false>,
                         cudaFuncAttributeMaxDynamicSharedMemorySize, SMEM_BYTES);

    ProjArgs none = {};

    // 1) splits
    {
        dim3 gi((BL * DD) / 1024, 3);
        cvt3<<<gi, 256>>>(q, k, v, qh, ql, kh, kl, vh, vl);
        dim3 gw((DD * DD) / 1024, 3);
        cvt3<<<gw, 256>>>(Wq, Wk, Wv, Wqh, Wql, Wkh, Wkl, Wvh, Wvl);
    }

    // 2a) q & k projections fused in one launch (z selects pointer set)
    {
        ProjArgs pa;
        pa.Ah0 = qh; pa.Al0 = ql; pa.Bh0 = Wqh; pa.Bl0 = Wql;
        pa.b0 = bq; pa.Ch0 = qph; pa.Cl0 = qpl;
        pa.Ah1 = kh; pa.Al1 = kl; pa.Bh1 = Wkh; pa.Bl1 = Wkl;
        pa.b1 = bk; pa.Ch1 = kph; pa.Cl1 = kpl;
        dim3 gqk(DD / 128, BL / 128, 2);
        gemm_mma<3, true><<<gqk, 256, SMEM_BYTES>>>(
            nullptr, nullptr, nullptr, nullptr, nullptr,
            nullptr, nullptr, nullptr, DD, DD, 0, 0, 0, 1, pa);
    }

    // 2b) v projection: 1-term (output is single fp16 plane anyway)
    {
        dim3 gv(DD / 128, BL / 128, 1);
        gemm_mma<1, false><<<gv, 256, SMEM_BYTES>>>(
            vh, nullptr, Wvh, nullptr, bv,
            nullptr, vpTh, nullptr, DD, DD, 0, 0, 0, 2, none);
    }

    // 3) E'[b] = exp(qp kp^T)*2^-26, fp16 single plane + colsums
    {
        dim3 gs(LL / 128, LL / 128, BB);
        gemm_mma<3, false><<<gs, 256, SMEM_BYTES>>>(
            qph, qpl, kph, kpl, nullptr,
            nullptr, Eh, nullptr,
            LL, DD,
            (size_t)LL * DD, (size_t)LL * DD,
            (size_t)LL * LL, 3, none);
    }

    // 4) rz = 1/colsum(E'); fold into vpT
    colsum_combine<<<BL / 256, 256>>>();
    scale_vpT<<<(BL * DD) / (8 * 256), 256>>>();

    // 5) out[b] = E'[b] @ vpT'[b]^T  (1-term plain fp16 GEMM)
    {
        dim3 go(DD / 128, LL / 128, BB);
        gemm_mma<1, false><<<go, 256, SMEM_BYTES>>>(
            Eh, nullptr, vpTh, nullptr, nullptr,
            out, nullptr, nullptr,
            DD, LL,
            (size_t)LL * LL, (size_t)DD * LL,
            (size_t)LL * DD, 0, none);
    }
}

// round 11
// speedup vs baseline: 1.5446x; 1.0175x over previous
#include <cuda_runtime.h>
#include <cuda_fp16.h>
#include <cstdint>
#include <math.h>

#define BB 8
#define LL 2048
#define DD 512
#define BL (BB*LL)

// ---------------------------------------------------------------------------
// Device scratch
// ---------------------------------------------------------------------------
__device__ __align__(256) __half g_Eh[(size_t)BB*LL*LL];  // E' = exp(S)*2^-26, fp16
__device__ __align__(256) __half g_qh[BL*DD], g_ql[BL*DD];
__device__ __align__(256) __half g_kh[BL*DD], g_kl[BL*DD];
__device__ __align__(256) __half g_vh[BL*DD];
__device__ __align__(256) __half g_Wqh[DD*DD], g_Wql[DD*DD];
__device__ __align__(256) __half g_Wkh[DD*DD], g_Wkl[DD*DD];
__device__ __align__(256) __half g_Wvh[DD*DD], g_Wvl[DD*DD];
__device__ __align__(256) __half g_qph[BL*DD], g_qpl[BL*DD];
__device__ __align__(256) __half g_kph[BL*DD], g_kpl[BL*DD];
__device__ __align__(256) __half g_vpTh[BL*DD];           // [B][D][L] single plane
__device__ __align__(256) float g_crcpz[BL];
__device__ __align__(256) float g_pz[16*BL];

// pointer set for z-fused projection launches
struct ProjArgs {
    const __half *Ah0, *Al0, *Bh0, *Bl0; const float* b0; __half *Ch0, *Cl0;
    const __half *Ah1, *Al1, *Bh1, *Bl1; const float* b1; __half *Ch1, *Cl1;
};

// ---------------------------------------------------------------------------
// Portable PTX helpers (sm_80+)
// ---------------------------------------------------------------------------
__device__ __forceinline__ uint32_t smem_u32(const void* p) {
    uint32_t a;
    asm("{ .reg .u64 t; cvta.to.shared.u64 t, %1; cvt.u32.u64 %0, t; }"
        : "=r"(a) : "l"(p));
    return a;
}

#define CP16(dst, src) \
    asm volatile("cp.async.cg.shared.global [%0], [%1], 16;" \
                 :: "r"(dst), "l"(src) : "memory")
#define CP_COMMIT() asm volatile("cp.async.commit_group;" ::: "memory")
#define CP_WAIT1()  asm volatile("cp.async.wait_group 1;" ::: "memory")

#define LDSM4(r0, r1, r2, r3, addr) \
    asm volatile("ldmatrix.sync.aligned.m8n8.x4.shared.b16 {%0,%1,%2,%3}, [%4];" \
                 : "=r"(r0), "=r"(r1), "=r"(r2), "=r"(r3) : "r"(addr))

#define MMAH(d, a, b) \
    asm volatile("mma.sync.aligned.m16n8k16.row.col.f32.f16.f16.f32 " \
                 "{%0,%1,%2,%3}, {%4,%5,%6,%7}, {%8,%9}, {%0,%1,%2,%3};" \
                 : "+f"((d)[0]), "+f"((d)[1]), "+f"((d)[2]), "+f"((d)[3]) \
                 : "r"((a)[0]), "r"((a)[1]), "r"((a)[2]), "r"((a)[3]), \
                   "r"((b)[0]), "r"((b)[1]))

__device__ __forceinline__ uint32_t packh2(float a, float b) {
    __half2 t = __floats2half2_rn(a, b);
    uint32_t u; memcpy(&u, &t, 4); return u;
}
__device__ __forceinline__ void split2h(float v0, float v1,
                                        uint32_t& h, uint32_t& l) {
    float h0 = __half2float(__float2half_rn(v0));
    float h1 = __half2float(__float2half_rn(v1));
    h = packh2(v0, v1);
    l = packh2(v0 - h0, v1 - h1);
}

// Fast exp * 2^-26 on the FMA pipe (rel err ~2e-6), clamped for fp16 storage
__device__ __forceinline__ float fast_exp_s26(float x) {
    float y = x * 1.4426950408889634f;
    float t = y + 12582912.f;
    int   n = __float_as_int(t) - 0x4B400000;
    t -= 12582912.f;
    float f = y - t;
    float p = 1.3333558146e-3f;
    p = fmaf(p, f, 9.6181291076e-3f);
    p = fmaf(p, f, 5.5504108664e-2f);
    p = fmaf(p, f, 2.4022650696e-1f);
    p = fmaf(p, f, 6.9314718056e-1f);
    p = fmaf(p, f, 1.0f);
    float e = __int_as_float(__float_as_int(p) + ((n - 26) << 23));
    return fminf(e, 60000.f);
}

#define STAGE_BYTES 32768
#define SMEM_BYTES 98304

// ---------------------------------------------------------------------------
// NT GEMM, fp16 split precision, mma.sync.m16n8k16, 3-stage cp.async ring.
// TERMS=3: Ah*Bh + Ah*Bl + Al*Bh, K-chunk 32 (4 planes x 8KB per stage).
// TERMS=1: Ah*Bh only,            K-chunk 64 (2 planes x 16KB per stage).
// ZSEL: pointer set chosen by blockIdx.z from ProjArgs (strides must be 0).
// mode 0: Cf fp32 row-major.
// mode 1: Ch/Cl fp16 planes row-major (+bias).
// mode 2: Ch fp16 SINGLE plane transposed -> [b][n][m%LL] (+bias).
// mode 3: Ch = exp(C)*2^-26 fp16 SINGLE plane (coalesced via smem) + colsums.
// ---------------------------------------------------------------------------
template<int TERMS, bool ZSEL>
__global__ void __launch_bounds__(256, 2) gemm_mma(
    const __half* __restrict__ Ah, const __half* __restrict__ Al,
    const __half* __restrict__ Bh, const __half* __restrict__ Bl,
    const float* __restrict__ bias,
    float* __restrict__ Cf,
    __half* __restrict__ Ch, __half* __restrict__ Cl,
    int N, int K,
    size_t sAz, size_t sBz, size_t sCz,
    int mode, ProjArgs pa)
{
    constexpr int KCH   = (TERMS == 1) ? 64 : 32;   // k-elems per stage
    constexpr int KS    = KCH / 16;                 // ks sub-iters per stage
    constexpr int ROWB  = KCH * 2;                  // bytes per smem row
    constexpr int PLANE = 128 * ROWB;               // plane bytes (8K or 16K)
    constexpr int NCH   = KCH / 8;                  // 16B chunks per row
    // plane offsets within a 32KB stage
    constexpr int PAH = 0;
    constexpr int PAL = (TERMS == 3) ? PLANE : 0;
    constexpr int PBH = (TERMS == 3) ? 2 * PLANE : PLANE;
    constexpr int PBL = (TERMS == 3) ? 3 * PLANE : 0;

    extern __shared__ char smem[];
    const uint32_t sbase = smem_u32(smem);
    const int tid  = threadIdx.x;
    const int lane = tid & 31;
    const int warp = tid >> 5;
    const int wm = (warp >> 1) * 32;
    const int wn = (warp & 1) * 64;
    const int m0 = blockIdx.y * 128, n0 = blockIdx.x * 128, bz = blockIdx.z;

    if (ZSEL) {
        if (bz == 1) {
            Ah = pa.Ah1; Al = pa.Al1; Bh = pa.Bh1; Bl = pa.Bl1;
            bias = pa.b1; Ch = pa.Ch1; Cl = pa.Cl1;
        } else {
            Ah = pa.Ah0; Al = pa.Al0; Bh = pa.Bh0; Bl = pa.Bl0;
            bias = pa.b0; Ch = pa.Ch0; Cl = pa.Cl0;
        }
    }

    // swizzled offset of (row r, 16B-chunk kc) within a plane
    auto swz = [](int r, int kc) -> uint32_t {
        if (TERMS == 3)
            return (uint32_t)(r * 64 + ((kc ^ ((r >> 1) & 3)) << 4));
        else
            return (uint32_t)(r * 128 + ((kc ^ (r & 7)) << 4));
    };

    // hoisted cp.async addressing: 128*NCH chunks per plane, 256 threads
    constexpr int CPI = (128 * NCH) / 256;          // 2 or 4 iters
    uint32_t dOff[CPI];
    size_t   gOff[CPI];
    #pragma unroll
    for (int i = 0; i < CPI; i++) {
        int idx = tid + i * 256;
        int r, c;
        if (TERMS == 3) { r = idx >> 2; c = idx & 3; }
        else            { r = idx >> 3; c = idx & 7; }
        dOff[i] = swz(r, c);
        gOff[i] = (size_t)r * K + c * 8;
    }
    // hoisted ldmatrix offsets
    uint32_t offA[KS][2], offB[KS][4];
    #pragma unroll
    for (int ks = 0; ks < KS; ks++) {
        int kc = ks * 2 + (lane >> 4);
        int rbase = (lane & 7) + ((lane >> 3) & 1) * 8;
        #pragma unroll
        for (int im = 0; im < 2; im++)
            offA[ks][im] = swz(wm + im * 16 + rbase, kc);
        #pragma unroll
        for (int j4 = 0; j4 < 4; j4++)
            offB[ks][j4] = swz(wn + j4 * 16 + rbase, kc);
    }

    const __half* pAh = Ah + bz * sAz + (size_t)m0 * K;
    const __half* pAl = (TERMS == 3) ? Al + bz * sAz + (size_t)m0 * K : nullptr;
    const __half* pBh = Bh + bz * sBz + (size_t)n0 * K;
    const __half* pBl = (TERMS == 3) ? Bl + bz * sBz + (size_t)n0 * K : nullptr;

    float acc[2][8][4];
    #pragma unroll
    for (int i = 0; i < 2; i++)
        #pragma unroll
        for (int j = 0; j < 8; j++)
            #pragma unroll
            for (int c = 0; c < 4; c++) acc[i][j][c] = 0.f;

#define LOAD_STAGE(slot, kt) do { \
    uint32_t so_ = sbase + (uint32_t)(slot) * STAGE_BYTES; \
    size_t ko_ = (size_t)(kt) * KCH; \
    _Pragma("unroll") \
    for (int i_ = 0; i_ < CPI; i_++) { \
        uint32_t d_ = so_ + dOff[i_]; \
        size_t g_ = gOff[i_] + ko_; \
        CP16(d_ + PAH, pAh + g_); \
        CP16(d_ + PBH, pBh + g_); \
        if (TERMS == 3) { \
            CP16(d_ + PAL, pAl + g_); \
            CP16(d_ + PBL, pBl + g_); \
        } \
    } \
} while (0)

    const int nk = K / KCH;
    LOAD_STAGE(0, 0); CP_COMMIT();
    LOAD_STAGE(1, 1); CP_COMMIT();

    int slot = 0, nslot = 2;
    for (int kt = 0; kt < nk; kt++) {
        CP_WAIT1();
        __syncthreads();
        if (kt + 2 < nk) LOAD_STAGE(nslot, kt + 2);
        CP_COMMIT();

        const uint32_t so = sbase + (uint32_t)slot * STAGE_BYTES;
        #pragma unroll
        for (int ks = 0; ks < KS; ks++) {
            uint32_t a_h[2][4], a_l[2][4];
            #pragma unroll
            for (int im = 0; im < 2; im++) {
                uint32_t ad = so + offA[ks][im];
                LDSM4(a_h[im][0], a_h[im][1], a_h[im][2], a_h[im][3], ad + PAH);
                if (TERMS == 3)
                    LDSM4(a_l[im][0], a_l[im][1], a_l[im][2], a_l[im][3], ad + PAL);
            }
            uint32_t b_h[8][2], b_l[8][2];
            #pragma unroll
            for (int j4 = 0; j4 < 4; j4++) {
                uint32_t bd = so + offB[ks][j4];
                LDSM4(b_h[2*j4][0], b_h[2*j4+1][0], b_h[2*j4][1], b_h[2*j4+1][1],
                      bd + PBH);
                if (TERMS == 3)
                    LDSM4(b_l[2*j4][0], b_l[2*j4+1][0], b_l[2*j4][1], b_l[2*j4+1][1],
                          bd + PBL);
            }
            #pragma unroll
            for (int im = 0; im < 2; im++)
                #pragma unroll
                for (int j = 0; j < 8; j++) MMAH(acc[im][j], a_h[im], b_h[j]);
            if (TERMS == 3) {
                #pragma unroll
                for (int im = 0; im < 2; im++)
                    #pragma unroll
                    for (int j = 0; j < 8; j++) MMAH(acc[im][j], a_h[im], b_l[j]);
                #pragma unroll
                for (int im = 0; im < 2; im++)
                    #pragma unroll
                    for (int j = 0; j < 8; j++) MMAH(acc[im][j], a_l[im], b_h[j]);
            }
        }
        slot = (slot == 2) ? 0 : slot + 1;
        nslot = (nslot == 2) ? 0 : nslot + 1;
    }
#undef LOAD_STAGE
    __syncthreads();

    __half* pCh = Ch + bz * sCz;
    __half* pCl = Cl ? Cl + bz * sCz : nullptr;

    if (mode == 0) {
        float* base = Cf + bz * sCz;
        #pragma unroll
        for (int im = 0; im < 2; im++) {
            int gm = m0 + wm + im * 16 + (lane >> 2);
            #pragma unroll
            for (int j = 0; j < 8; j++) {
                int gn = n0 + wn + j * 8 + 2 * (lane & 3);
                *reinterpret_cast<float2*>(base + (size_t)gm * N + gn) =
                    make_float2(acc[im][j][0], acc[im][j][1]);
                *reinterpret_cast<float2*>(base + (size_t)(gm + 8) * N + gn) =
                    make_float2(acc[im][j][2], acc[im][j][3]);
            }
        }
    } else if (mode == 1) {
        #pragma unroll
        for (int im = 0; im < 2; im++) {
            int gm = m0 + wm + im * 16 + (lane >> 2);
            #pragma unroll
            for (int j = 0; j < 8; j++) {
                int gn = n0 + wn + j * 8 + 2 * (lane & 3);
                float b0 = bias[gn], b1 = bias[gn + 1];
                uint32_t h, l;
                split2h(acc[im][j][0] + b0, acc[im][j][1] + b1, h, l);
                *reinterpret_cast<uint32_t*>(pCh + (size_t)gm * N + gn) = h;
                *reinterpret_cast<uint32_t*>(pCl + (size_t)gm * N + gn) = l;
                split2h(acc[im][j][2] + b0, acc[im][j][3] + b1, h, l);
                *reinterpret_cast<uint32_t*>(pCh + (size_t)(gm + 8) * N + gn) = h;
                *reinterpret_cast<uint32_t*>(pCl + (size_t)(gm + 8) * N + gn) = l;
            }
        }
    } else if (mode == 2) {
        float* sC = reinterpret_cast<float*>(smem);
        #pragma unroll
        for (int im = 0; im < 2; im++) {
            int rr = wm + im * 16 + (lane >> 2);
            #pragma unroll
            for (int j = 0; j < 8; j++) {
                int cc = wn + j * 8 + 2 * (lane & 3);
                sC[rr * 128 + cc]           = acc[im][j][0];
                sC[rr * 128 + cc + 1]       = acc[im][j][1];
                sC[(rr + 8) * 128 + cc]     = acc[im][j][2];
                sC[(rr + 8) * 128 + cc + 1] = acc[im][j][3];
            }
        }
        __syncthreads();
        const int nl = tid & 127;
        const int mh = tid >> 7;
        const float bv = bias ? bias[n0 + nl] : 0.f;
        const int b  = m0 >> 11;
        const int l0 = (m0 & (LL - 1)) + mh * 64;
        size_t base = ((size_t)b * DD + (n0 + nl)) * (size_t)LL + l0;
        for (int i = 0; i < 64; i += 8) {
            uint32_t w[4];
            #pragma unroll
            for (int p = 0; p < 4; p++) {
                float v0 = sC[(mh * 64 + i + 2 * p)     * 128 + nl] + bv;
                float v1 = sC[(mh * 64 + i + 2 * p + 1) * 128 + nl] + bv;
                w[p] = packh2(v0, v1);
            }
            *reinterpret_cast<uint4*>(Ch + base + i) =
                make_uint4(w[0], w[1], w[2], w[3]);
        }
    } else {
        // mode 3: E' = exp(S)*2^-26 fp16 single plane via smem; fp32 colsums
        const int STR = 136;
        __half* sE = reinterpret_cast<__half*>(smem);
        float* sPart = reinterpret_cast<float*>(smem + 128 * STR * 2 + 64);
        float cs[8][2];
        #pragma unroll
        for (int j = 0; j < 8; j++) { cs[j][0] = 0.f; cs[j][1] = 0.f; }
        #pragma unroll
        for (int im = 0; im < 2; im++) {
            int r0 = wm + im * 16 + (lane >> 2);
            #pragma unroll
            for (int j = 0; j < 8; j++) {
                int c0 = wn + j * 8 + 2 * (lane & 3);
                float e0 = fast_exp_s26(acc[im][j][0]);
                float e1 = fast_exp_s26(acc[im][j][1]);
                float e2 = fast_exp_s26(acc[im][j][2]);
                float e3 = fast_exp_s26(acc[im][j][3]);
                *reinterpret_cast<uint32_t*>(sE + r0 * STR + c0)       = packh2(e0, e1);
                *reinterpret_cast<uint32_t*>(sE + (r0 + 8) * STR + c0) = packh2(e2, e3);
                cs[j][0] += e0 + e2;
                cs[j][1] += e1 + e3;
            }
        }
        #pragma unroll
        for (int j = 0; j < 8; j++) {
            #pragma unroll
            for (int off = 4; off <= 16; off <<= 1) {
                cs[j][0] += __shfl_xor_sync(0xffffffffu, cs[j][0], off);
                cs[j][1] += __shfl_xor_sync(0xffffffffu, cs[j][1], off);
            }
        }
        __syncthreads();
        {
            int row = tid >> 1;
            int seg = (tid & 1) * 64;
            size_t gb = (size_t)(m0 + row) * N + n0 + seg;
            #pragma unroll
            for (int i = 0; i < 8; i++) {
                uint4 w = *reinterpret_cast<uint4*>(sE + row * STR + seg + i * 8);
                *reinterpret_cast<uint4*>(pCh + gb + i * 8) = w;
            }
        }
        if (lane < 4) {
            int mwarp = warp >> 1;
            #pragma unroll
            for (int j = 0; j < 8; j++) {
                int col = wn + j * 8 + 2 * (lane & 3);
                sPart[mwarp * 128 + col]     = cs[j][0];
                sPart[mwarp * 128 + col + 1] = cs[j][1];
            }
        }
        __syncthreads();
        if (tid < 128) {
            float tot = sPart[tid] + sPart[128 + tid] +
                        sPart[256 + tid] + sPart[384 + tid];
            g_pz[(size_t)blockIdx.y * BL + bz * LL + n0 + tid] = tot;
        }
    }
}

// ---------------------------------------------------------------------------
// fused fp32 -> fp16 hi/lo split for 3 arrays (lo plane optional per array)
// ---------------------------------------------------------------------------
__global__ void __launch_bounds__(256) cvt3(
    const float* __restrict__ s0, const float* __restrict__ s1,
    const float* __restrict__ s2,
    __half* __restrict__ h0, __half* __restrict__ l0,
    __half* __restrict__ h1, __half* __restrict__ l1,
    __half* __restrict__ h2, __half* __restrict__ l2)
{
    const float* s = (blockIdx.y == 0) ? s0 : (blockIdx.y == 1) ? s1 : s2;
    __half* h = (blockIdx.y == 0) ? h0 : (blockIdx.y == 1) ? h1 : h2;
    __half* l = (blockIdx.y == 0) ? l0 : (blockIdx.y == 1) ? l1 : l2;
    size_t i = (size_t)blockIdx.x * 256 + threadIdx.x;
    float4 v = reinterpret_cast<const float4*>(s)[i];
    uint32_t ha, la, hb, lb;
    split2h(v.x, v.y, ha, la);
    split2h(v.z, v.w, hb, lb);
    reinterpret_cast<uint32_t*>(h)[2 * i + 0] = ha;
    reinterpret_cast<uint32_t*>(h)[2 * i + 1] = hb;
    if (l) {
        reinterpret_cast<uint32_t*>(l)[2 * i + 0] = la;
        reinterpret_cast<uint32_t*>(l)[2 * i + 1] = lb;
    }
}

__global__ void __launch_bounds__(256) colsum_combine()
{
    const int c = blockIdx.x * 256 + threadIdx.x;
    float z = 0.f;
    #pragma unroll
    for (int s = 0; s < 16; s++) z += g_pz[(size_t)s * BL + c];
    g_crcpz[c] = 1.f / z;
}

// vpT[b][d][l] *= rz[b][l], single fp16 plane
__global__ void __launch_bounds__(256) scale_vpT()
{
    size_t idx = (size_t)blockIdx.x * 256 + threadIdx.x;
    size_t e0  = idx * 8;
    int l   = (int)(e0 & (LL - 1));
    int row = (int)(e0 >> 11);
    int b   = row >> 9;
    uint4 hv = reinterpret_cast<uint4*>(g_vpTh)[idx];
    const float* rz = &g_crcpz[b * LL + l];
    uint32_t hw[4] = {hv.x, hv.y, hv.z, hv.w};
    #pragma unroll
    for (int p = 0; p < 4; p++) {
        __half2 hh;
        memcpy(&hh, &hw[p], 4);
        float v0 = __half2float(hh.x) * rz[2 * p];
        float v1 = __half2float(hh.y) * rz[2 * p + 1];
        hw[p] = packh2(v0, v1);
    }
    reinterpret_cast<uint4*>(g_vpTh)[idx] = make_uint4(hw[0], hw[1], hw[2], hw[3]);
}

// ---------------------------------------------------------------------------
extern "C" void kernel_launch(void* const* d_in, const int* in_sizes, int n_in,
                              void* d_out, int out_size)
{
    const float* q  = (const float*)d_in[0];
    const float* k  = (const float*)d_in[1];
    const float* v  = (const float*)d_in[2];
    const float* Wq = (const float*)d_in[3];
    const float* bq = (const float*)d_in[4];
    const float* Wk = (const float*)d_in[5];
    const float* bk = (const float*)d_in[6];
    const float* Wv = (const float*)d_in[7];
    const float* bv = (const float*)d_in[8];
    float* out = (float*)d_out;

    __half *qh, *ql, *kh, *kl, *vh;
    __half *Wqh, *Wql, *Wkh, *Wkl, *Wvh, *Wvl;
    __half *qph, *qpl, *kph, *kpl, *vpTh, *Eh;
    cudaGetSymbolAddress((void**)&qh, g_qh);   cudaGetSymbolAddress((void**)&ql, g_ql);
    cudaGetSymbolAddress((void**)&kh, g_kh);   cudaGetSymbolAddress((void**)&kl, g_kl);
    cudaGetSymbolAddress((void**)&vh, g_vh);
    cudaGetSymbolAddress((void**)&Wqh, g_Wqh); cudaGetSymbolAddress((void**)&Wql, g_Wql);
    cudaGetSymbolAddress((void**)&Wkh, g_Wkh); cudaGetSymbolAddress((void**)&Wkl, g_Wkl);
    cudaGetSymbolAddress((void**)&Wvh, g_Wvh); cudaGetSymbolAddress((void**)&Wvl, g_Wvl);
    cudaGetSymbolAddress((void**)&qph, g_qph); cudaGetSymbolAddress((void**)&qpl, g_qpl);
    cudaGetSymbolAddress((void**)&kph, g_kph); cudaGetSymbolAddress((void**)&kpl, g_kpl);
    cudaGetSymbolAddress((void**)&vpTh, g_vpTh);
    cudaGetSymbolAddress((void**)&Eh, g_Eh);

    cudaFuncSetAttribute((const void*)gemm_mma<3, false>,
                         cudaFuncAttributeMaxDynamicSharedMemorySize, SMEM_BYTES);
    cudaFuncSetAttribute((const void*)gemm_mma<3, true>,
                         cudaFuncAttributeMaxDynamicSharedMemorySize, SMEM_BYTES);
    cudaFuncSetAttribute((const void*)gemm_mma<1, false>,
                         cudaFuncAttributeMaxDynamicSharedMemorySize, SMEM_BYTES);

    ProjArgs none = {};

    // 1) splits (v: hi plane only)
    {
        dim3 gi((BL * DD) / 1024, 3);
        cvt3<<<gi, 256>>>(q, k, v, qh, ql, kh, kl, vh, nullptr);
        dim3 gw((DD * DD) / 1024, 3);
        cvt3<<<gw, 256>>>(Wq, Wk, Wv, Wqh, Wql, Wkh, Wkl, Wvh, Wvl);
    }

    // 2a) q & k projections fused in one launch (z selects pointer set)
    {
        ProjArgs pa;
        pa.Ah0 = qh; pa.Al0 = ql; pa.Bh0 = Wqh; pa.Bl0 = Wql;
        pa.b0 = bq; pa.Ch0 = qph; pa.Cl0 = qpl;
        pa.Ah1 = kh; pa.Al1 = kl; pa.Bh1 = Wkh; pa.Bl1 = Wkl;
        pa.b1 = bk; pa.Ch1 = kph; pa.Cl1 = kpl;
        dim3 gqk(DD / 128, BL / 128, 2);
        gemm_mma<3, true><<<gqk, 256, SMEM_BYTES>>>(
            nullptr, nullptr, nullptr, nullptr, nullptr,
            nullptr, nullptr, nullptr, DD, DD, 0, 0, 0, 1, pa);
    }

    // 2b) v projection: 1-term (K-chunk 64 pipeline)
    {
        dim3 gv(DD / 128, BL / 128, 1);
        gemm_mma<1, false><<<gv, 256, SMEM_BYTES>>>(
            vh, nullptr, Wvh, nullptr, bv,
            nullptr, vpTh, nullptr, DD, DD, 0, 0, 0, 2, none);
    }

    // 3) E'[b] = exp(qp kp^T)*2^-26, fp16 single plane + colsums
    {
        dim3 gs(LL / 128, LL / 128, BB);
        gemm_mma<3, false><<<gs, 256, SMEM_BYTES>>>(
            qph, qpl, kph, kpl, nullptr,
            nullptr, Eh, nullptr,
            LL, DD,
            (size_t)LL * DD, (size_t)LL * DD,
            (size_t)LL * LL, 3, none);
    }

    // 4) rz = 1/colsum(E'); fold into vpT
    colsum_combine<<<BL / 256, 256>>>();
    scale_vpT<<<(BL * DD) / (8 * 256), 256>>>();

    // 5) out[b] = E'[b] @ vpT'[b]^T  (1-term, K-chunk 64 pipeline)
    {
        dim3 go(DD / 128, LL / 128, BB);
        gemm_mma<1, false><<<go, 256, SMEM_BYTES>>>(
            Eh, nullptr, vpTh, nullptr, nullptr,
            out, nullptr, nullptr,
            DD, LL,
            (size_t)LL * LL, (size_t)DD * LL,
            (size_t)LL * DD, 0, none);
    }
}